// round 1
// baseline (speedup 1.0000x reference)
#include <cuda_runtime.h>

#define BB 8
#define NN 2048
#define FF 256

// ---- scratch (module-scope device globals; no runtime allocation) ----
__device__ float g_Wh[BB * NN * FF];            // 16 MB
__device__ float g_s1[BB * NN];
__device__ float g_s2[BB * NN];
__device__ float g_m[BB * NN];
__device__ float g_iz[BB * NN];
__device__ unsigned long long g_mask[NN * 32];  // 2048 bits per row

// ---- packed f32x2 helpers (Blackwell dual-fp32 path) ----
__device__ __forceinline__ unsigned long long pk2(float x, float y) {
    unsigned long long r;
    asm("mov.b64 %0, {%1, %2};" : "=l"(r) : "f"(x), "f"(y));
    return r;
}
__device__ __forceinline__ float2 upk2(unsigned long long v) {
    float2 r;
    asm("mov.b64 {%0, %1}, %2;" : "=f"(r.x), "=f"(r.y) : "l"(v));
    return r;
}
#define FMA2(d, a, b) asm("fma.rn.f32x2 %0, %1, %2, %0;" : "+l"(d) : "l"(a), "l"(b))

// FFMA-only expf (no MUFU). Valid for x in [-80, 10], rel err ~3e-6.
__device__ __forceinline__ float fexp(float x) {
    const float L2E = 1.4426950408889634f;
    float t = fmaf(x, L2E, 12582912.0f);   // 1.5*2^23 magic: round-to-nearest int
    int   k = __float_as_int(t);           // low bits hold round(x*log2e)
    float r = t - 12582912.0f;
    float f = fmaf(x, L2E, -r);            // f in [-0.5, 0.5]
    float p = 1.33335581e-3f;
    p = fmaf(p, f, 9.61812910e-3f);
    p = fmaf(p, f, 5.55041086e-2f);
    p = fmaf(p, f, 2.40226507e-1f);
    p = fmaf(p, f, 6.93147182e-1f);
    p = fmaf(p, f, 1.0f);                  // p = 2^f
    return __int_as_float(__float_as_int(p) + (k << 23));  // scale by 2^round
}

// ========================================================================
// Kernel 1: Wh = h @ W  (+ fused s1 = Wh@a1, s2 = Wh@a2)
// Block: 64 rows x 256 cols, 256 threads; thread: 2 rows x 16 f-pairs.
// ========================================================================
__global__ void __launch_bounds__(256)
k_gemm1(const float* __restrict__ h, const float* __restrict__ W,
        const float* __restrict__ a) {
    __shared__ __align__(16) float hs[16][66];   // [k][row], padded
    __shared__ __align__(16) float Ws[16 * 256]; // [k][f]
    __shared__ float s1b[64], s2b[64];
    __shared__ float as1[256], as2[256];
    const int b = blockIdx.y, it = blockIdx.x;
    const int i0 = it * 64;
    const int t = threadIdx.x;
    const int fg = t & 7, rg = t >> 3;           // rows rg*2 .. rg*2+1

    if (t < 64) { s1b[t] = 0.f; s2b[t] = 0.f; }
    as1[t] = a[t];
    as2[t] = a[256 + t];

    unsigned long long acc[2][16];
#pragma unroll
    for (int k2 = 0; k2 < 2; ++k2)
#pragma unroll
        for (int fp = 0; fp < 16; ++fp) acc[k2][fp] = 0ull;

    const float* hb = h + ((size_t)b * NN + i0) * FF;

    for (int k0 = 0; k0 < FF; k0 += 16) {
        __syncthreads();
        // h tile (transposed into smem): 64 rows x 16 k
#pragma unroll
        for (int q = 0; q < 4; ++q) {
            int idx = t + q * 256;            // 0..1023
            int r = idx >> 4, kk = idx & 15;
            hs[kk][r] = hb[r * FF + k0 + kk];
        }
        // W tile: 16 x 256 (row-major, no transpose)
        const float4* wg = (const float4*)(W + k0 * FF);
#pragma unroll
        for (int q = 0; q < 4; ++q)
            ((float4*)Ws)[t + q * 256] = wg[t + q * 256];
        __syncthreads();

#pragma unroll 4
        for (int kk = 0; kk < 16; ++kk) {
            float2 hv = *(const float2*)&hs[kk][rg * 2];
            unsigned long long hp0 = pk2(hv.x, hv.x);
            unsigned long long hp1 = pk2(hv.y, hv.y);
            const unsigned long long* wrow =
                (const unsigned long long*)(Ws + kk * 256);
#pragma unroll
            for (int fp = 0; fp < 16; ++fp) {
                unsigned long long wp = wrow[fp * 8 + fg];  // interleaved f
                FMA2(acc[0][fp], hp0, wp);
                FMA2(acc[1][fp], hp1, wp);
            }
        }
    }

    // epilogue: store Wh, partial dots with a1/a2
    float* whb = g_Wh + ((size_t)b * NN + i0) * FF;
    float p1[2] = {0.f, 0.f}, p2[2] = {0.f, 0.f};
#pragma unroll
    for (int fp = 0; fp < 16; ++fp) {
        int f = 2 * (fp * 8 + fg);
        float a1x = as1[f], a1y = as1[f + 1];
        float a2x = as2[f], a2y = as2[f + 1];
#pragma unroll
        for (int k2 = 0; k2 < 2; ++k2) {
            float2 v = upk2(acc[k2][fp]);
            *(float2*)&whb[(rg * 2 + k2) * FF + f] = v;
            p1[k2] += v.x * a1x + v.y * a1y;
            p2[k2] += v.x * a2x + v.y * a2y;
        }
    }
    atomicAdd(&s1b[rg * 2 + 0], p1[0]);
    atomicAdd(&s1b[rg * 2 + 1], p1[1]);
    atomicAdd(&s2b[rg * 2 + 0], p2[0]);
    atomicAdd(&s2b[rg * 2 + 1], p2[1]);
    __syncthreads();
    if (t < 64) {
        g_s1[b * NN + i0 + t] = s1b[t];
        g_s2[b * NN + i0 + t] = s2b[t];
    }
}

// ========================================================================
// Kernel 2: pack mask bits: mask[i][j] = adj[i][j] > 0 || i == j
// one warp per row; thread -> one 64-bit word
// ========================================================================
__global__ void k_mask(const int* __restrict__ adj) {
    int idx = blockIdx.x * 256 + threadIdx.x;   // 0..65535
    int i = idx >> 5, w = idx & 31;
    const int* row = adj + (size_t)i * NN + w * 64;
    unsigned long long m = 0ull;
#pragma unroll 8
    for (int bb = 0; bb < 64; ++bb)
        if (row[bb] > 0) m |= 1ull << bb;
    int d = i - w * 64;
    if (d >= 0 && d < 64) m |= 1ull << d;
    g_mask[idx] = m;
}

// ========================================================================
// Kernel 3: per-row softmax stats: m = max_j e, invZ = 1/sum_j exp(e-m)
// grid (N, B), block 256 (8 j's per thread)
// ========================================================================
__global__ void __launch_bounds__(256)
k_stats() {
    const int i = blockIdx.x, b = blockIdx.y, t = threadIdx.x;
    __shared__ float red[8];
    __shared__ float bval;
    const float s1v = g_s1[b * NN + i];
    const float* s2r = g_s2 + b * NN;
    const unsigned long long* mrow = g_mask + i * 32;
    float e[8], mk[8];
    float mx = -3e38f;
#pragma unroll
    for (int q = 0; q < 8; ++q) {
        int j = t + q * 256;
        float x = s1v + s2r[j];
        x = fmaxf(x, 0.2f * x);                     // leaky_relu(0.2)
        unsigned long long wd = mrow[j >> 6];
        float f = (float)((wd >> (j & 63)) & 1ull);
        e[q] = x; mk[q] = f;
        mx = fmaxf(mx, f > 0.f ? x : -3e38f);
    }
#pragma unroll
    for (int off = 16; off > 0; off >>= 1)
        mx = fmaxf(mx, __shfl_xor_sync(0xffffffffu, mx, off));
    if ((t & 31) == 0) red[t >> 5] = mx;
    __syncthreads();
    if (t == 0) {
        float v = red[0];
        for (int w2 = 1; w2 < 8; ++w2) v = fmaxf(v, red[w2]);
        bval = v;
    }
    __syncthreads();
    const float M = bval;
    float s = 0.f;
#pragma unroll
    for (int q = 0; q < 8; ++q)
        s += mk[q] * fexp(fminf(fmaxf(e[q] - M, -80.f), 8.f));
#pragma unroll
    for (int off = 16; off > 0; off >>= 1)
        s += __shfl_xor_sync(0xffffffffu, s, off);
    if ((t & 31) == 0) red[t >> 5] = s;
    __syncthreads();
    if (t == 0) {
        float v = 0.f;
        for (int w2 = 0; w2 < 8; ++w2) v += red[w2];
        g_m[b * NN + i] = M;
        g_iz[b * NN + i] = 1.0f / v;   // diag always in mask -> v >= 1
    }
}

// ========================================================================
// Kernel 4: out = elu(P @ Wh), P computed on the fly (normalized softmax)
// Block: 64 i-rows x 256 f, 256 threads; j tiled by 32.
// Thread: 2 rows x 16 f-pairs (f32x2 accumulators).
// ========================================================================
__global__ void __launch_bounds__(256)
k_attn(float* __restrict__ out) {
    __shared__ __align__(16) float whs[32 * 256];  // 32 KB j-tile of Wh
    __shared__ float ps[64][33];                   // p tile, padded
    __shared__ float s1s[64], ms[64], zs[64];
    __shared__ float s2s[32];
    const int b = blockIdx.y, it = blockIdx.x;
    const int i0 = it * 64;
    const int t = threadIdx.x;
    const int fg = t & 7, rg = t >> 3;

    if (t < 64) {
        s1s[t] = g_s1[b * NN + i0 + t];
        ms[t]  = g_m [b * NN + i0 + t];
        zs[t]  = g_iz[b * NN + i0 + t];
    }
    unsigned long long acc[2][16];
#pragma unroll
    for (int k2 = 0; k2 < 2; ++k2)
#pragma unroll
        for (int fp = 0; fp < 16; ++fp) acc[k2][fp] = 0ull;

    const float* whB = g_Wh + (size_t)b * NN * FF;
    const float* s2B = g_s2 + b * NN;
    const int jj_p = t & 31;

    for (int j0 = 0; j0 < NN; j0 += 32) {
        __syncthreads();
        // Wh tile: 32 rows x 256 f
        const float4* src = (const float4*)(whB + (size_t)j0 * FF);
#pragma unroll
        for (int q = 0; q < 8; ++q)
            ((float4*)whs)[t + q * 256] = src[t + q * 256];
        if (t < 32) s2s[t] = s2B[j0 + t];
        __syncthreads();

        // p tile: 64 x 32, 8 values per thread (FFMA-only exp)
        {
            float s2v = s2s[jj_p];
            int wsh  = (j0 + jj_p) & 63;
            int widx = (j0 + jj_p) >> 6;
#pragma unroll
            for (int q = 0; q < 8; ++q) {
                int row = (t >> 5) + q * 8;
                float x = s1s[row] + s2v;
                x = fmaxf(x, 0.2f * x);
                unsigned long long wd =
                    g_mask[(size_t)(i0 + row) * 32 + widx];
                float mkf = (float)((wd >> wsh) & 1ull);
                ps[row][jj_p] = mkf * zs[row] *
                    fexp(fminf(fmaxf(x - ms[row], -80.f), 8.f));
            }
        }
        __syncthreads();

        // accumulate: acc += p(:,jj) * Wh(jj,:)
#pragma unroll 4
        for (int jj = 0; jj < 32; ++jj) {
            float w0 = ps[rg * 2 + 0][jj];
            float w1 = ps[rg * 2 + 1][jj];
            unsigned long long wp0 = pk2(w0, w0);
            unsigned long long wp1 = pk2(w1, w1);
            const unsigned long long* wrow =
                (const unsigned long long*)(whs + jj * 256);
#pragma unroll
            for (int fp = 0; fp < 16; ++fp) {
                unsigned long long whp = wrow[fp * 8 + fg];
                FMA2(acc[0][fp], wp0, whp);
                FMA2(acc[1][fp], wp1, whp);
            }
        }
    }

    // epilogue: ELU + store
    float* ob = out + ((size_t)b * NN + i0) * FF;
#pragma unroll
    for (int fp = 0; fp < 16; ++fp) {
        int f = 2 * (fp * 8 + fg);
#pragma unroll
        for (int k2 = 0; k2 < 2; ++k2) {
            float2 v = upk2(acc[k2][fp]);
            v.x = v.x > 0.f ? v.x : fexp(fmaxf(v.x, -80.f)) - 1.f;
            v.y = v.y > 0.f ? v.y : fexp(fmaxf(v.y, -80.f)) - 1.f;
            *(float2*)&ob[(rg * 2 + k2) * FF + f] = v;
        }
    }
}

// ========================================================================
extern "C" void kernel_launch(void* const* d_in, const int* in_sizes, int n_in,
                              void* d_out, int out_size) {
    const float* h   = (const float*)d_in[0];
    const int*   adj = (const int*)d_in[1];
    const float* W   = (const float*)d_in[2];
    const float* a   = (const float*)d_in[3];
    float* out = (float*)d_out;

    k_gemm1<<<dim3(NN / 64, BB), 256>>>(h, W, a);
    k_mask <<<NN * 32 / 256, 256>>>(adj);
    k_stats<<<dim3(NN, BB), 256>>>();
    k_attn <<<dim3(NN / 64, BB), 256>>>(out);
}

// round 2
// speedup vs baseline: 1.4235x; 1.4235x over previous
#include <cuda_runtime.h>

#define BB 8
#define NN 2048
#define FF 256

// ---- scratch (module-scope device globals; no runtime allocation) ----
__device__ float g_Wh[BB * NN * FF];            // 16 MB
__device__ float g_s1[BB * NN];
__device__ float g_s2[BB * NN];
__device__ float g_m[BB * NN];
__device__ float g_iz[BB * NN];
__device__ unsigned long long g_mask[NN * 32];  // 2048 bits per row

typedef unsigned long long ull;

// ---- packed f32x2 helpers (Blackwell dual-fp32 path) ----
__device__ __forceinline__ ull pk2(float x, float y) {
    ull r;
    asm("mov.b64 %0, {%1, %2};" : "=l"(r) : "f"(x), "f"(y));
    return r;
}
__device__ __forceinline__ float2 upk2(ull v) {
    float2 r;
    asm("mov.b64 {%0, %1}, %2;" : "=f"(r.x), "=f"(r.y) : "l"(v));
    return r;
}
#define FMA2(d, a, b) asm("fma.rn.f32x2 %0, %1, %2, %0;" : "+l"(d) : "l"(a), "l"(b))

// FFMA-only expf (no MUFU). Valid for x in [-80, 10], rel err ~3e-6.
__device__ __forceinline__ float fexp(float x) {
    const float L2E = 1.4426950408889634f;
    float t = fmaf(x, L2E, 12582912.0f);   // 1.5*2^23 magic: round-to-nearest int
    int   k = __float_as_int(t);
    float r = t - 12582912.0f;
    float f = fmaf(x, L2E, -r);            // f in [-0.5, 0.5]
    float p = 1.33335581e-3f;
    p = fmaf(p, f, 9.61812910e-3f);
    p = fmaf(p, f, 5.55041086e-2f);
    p = fmaf(p, f, 2.40226507e-1f);
    p = fmaf(p, f, 6.93147182e-1f);
    p = fmaf(p, f, 1.0f);                  // p = 2^f
    return __int_as_float(__float_as_int(p) + (k << 23));
}

__device__ __forceinline__ float elu1(float x) {
    return x > 0.f ? x : fexp(fmaxf(x, -80.f)) - 1.f;
}

// ========================================================================
// Kernel 1: Wh = h @ W  (+ fused s1 = Wh@a1, s2 = Wh@a2)
// 128 threads; block tile 64 rows x 256 f; k-tile 32.
// Thread tile: 8 rows x 16 f (64 f32x2 accumulators).
// Lane layout: fg = (t>>1)&15, rg = (t&1)|((t>>5)<<1)  -> adjacent lanes
// share fg => smem reads are 2-way broadcast, full 128B/cyc crossbar rate.
// ========================================================================
__global__ void __launch_bounds__(128)
k_gemm1(const float* __restrict__ h, const float* __restrict__ W,
        const float* __restrict__ a) {
    __shared__ __align__(16) float Ws[32 * 256];   // 32 KB [k][f]
    __shared__ __align__(16) float hs[32][68];     // [k][row], 16B-aligned rows
    __shared__ float as1[256], as2[256];
    const int b = blockIdx.y, i0 = blockIdx.x * 64;
    const int t = threadIdx.x;
    const int fg = (t >> 1) & 15;
    const int rg = (t & 1) | ((t >> 5) << 1);      // 0..7 -> rows rg*8..rg*8+7

    as1[t] = a[t];         as1[t + 128] = a[t + 128];
    as2[t] = a[256 + t];   as2[t + 128] = a[384 + t];

    ull acc[8][8];
#pragma unroll
    for (int r = 0; r < 8; ++r)
#pragma unroll
        for (int c = 0; c < 8; ++c) acc[r][c] = 0ull;

    const int lrow = t & 63, kq = t >> 6;          // fill-phase mapping
    const float* hrow = h + ((size_t)b * NN + i0 + lrow) * FF;

    for (int k0 = 0; k0 < FF; k0 += 32) {
        __syncthreads();
        // Ws tile: 32 x 256
        const float4* wsrc = (const float4*)(W + (size_t)k0 * FF);
#pragma unroll
        for (int q = 0; q < 16; ++q)
            ((float4*)Ws)[t + q * 128] = wsrc[t + q * 128];
        // h tile transposed: hs[kk][row]
#pragma unroll
        for (int q = 0; q < 4; ++q) {
            float4 hv = *(const float4*)&hrow[k0 + kq * 16 + q * 4];
            hs[kq * 16 + q * 4 + 0][lrow] = hv.x;
            hs[kq * 16 + q * 4 + 1][lrow] = hv.y;
            hs[kq * 16 + q * 4 + 2][lrow] = hv.z;
            hs[kq * 16 + q * 4 + 3][lrow] = hv.w;
        }
        __syncthreads();

#pragma unroll 8
        for (int kk = 0; kk < 32; ++kk) {
            const ulonglong2* wrow = (const ulonglong2*)(Ws + kk * 256);
            ulonglong2 w0 = wrow[fg];
            ulonglong2 w1 = wrow[fg + 16];
            ulonglong2 w2 = wrow[fg + 32];
            ulonglong2 w3 = wrow[fg + 48];
            float4 pa = *(const float4*)&hs[kk][rg * 8];
            float4 pb = *(const float4*)&hs[kk][rg * 8 + 4];
            float pv[8] = {pa.x, pa.y, pa.z, pa.w, pb.x, pb.y, pb.z, pb.w};
#pragma unroll
            for (int r = 0; r < 8; ++r) {
                ull pp = pk2(pv[r], pv[r]);
                FMA2(acc[r][0], pp, w0.x); FMA2(acc[r][1], pp, w0.y);
                FMA2(acc[r][2], pp, w1.x); FMA2(acc[r][3], pp, w1.y);
                FMA2(acc[r][4], pp, w2.x); FMA2(acc[r][5], pp, w2.y);
                FMA2(acc[r][6], pp, w3.x); FMA2(acc[r][7], pp, w3.y);
            }
        }
    }

    // epilogue: store Wh + partial dots with a1/a2, reduce across fg lanes
    float* whb = g_Wh + ((size_t)b * NN + i0 + rg * 8) * FF;
    float p1[8], p2[8];
#pragma unroll
    for (int r = 0; r < 8; ++r) { p1[r] = 0.f; p2[r] = 0.f; }
#pragma unroll
    for (int fq = 0; fq < 4; ++fq) {
        int c = (fq * 16 + fg) * 4;
        float a10 = as1[c], a11 = as1[c + 1], a12 = as1[c + 2], a13 = as1[c + 3];
        float a20 = as2[c], a21 = as2[c + 1], a22 = as2[c + 2], a23 = as2[c + 3];
#pragma unroll
        for (int r = 0; r < 8; ++r) {
            float2 lo = upk2(acc[r][2 * fq]);
            float2 hi = upk2(acc[r][2 * fq + 1]);
            float4 v = make_float4(lo.x, lo.y, hi.x, hi.y);
            *(float4*)&whb[r * FF + c] = v;
            p1[r] += v.x * a10 + v.y * a11 + v.z * a12 + v.w * a13;
            p2[r] += v.x * a20 + v.y * a21 + v.z * a22 + v.w * a23;
        }
    }
#pragma unroll
    for (int off = 2; off <= 16; off <<= 1)
#pragma unroll
        for (int r = 0; r < 8; ++r) {
            p1[r] += __shfl_xor_sync(0xffffffffu, p1[r], off);
            p2[r] += __shfl_xor_sync(0xffffffffu, p2[r], off);
        }
    if (fg == 0) {
#pragma unroll
        for (int r = 0; r < 8; ++r) {
            g_s1[b * NN + i0 + rg * 8 + r] = p1[r];
            g_s2[b * NN + i0 + rg * 8 + r] = p2[r];
        }
    }
}

// ========================================================================
// Kernel 2: pack mask bits: mask[i][j] = adj[i][j] > 0 || i == j
// ========================================================================
__global__ void k_mask(const int* __restrict__ adj) {
    int idx = blockIdx.x * 256 + threadIdx.x;   // 0..65535
    int i = idx >> 5, w = idx & 31;
    const int* row = adj + (size_t)i * NN + w * 64;
    ull m = 0ull;
#pragma unroll 8
    for (int bb = 0; bb < 64; ++bb)
        if (row[bb] > 0) m |= 1ull << bb;
    int d = i - w * 64;
    if (d >= 0 && d < 64) m |= 1ull << d;
    g_mask[idx] = m;
}

// ========================================================================
// Kernel 3: per-row softmax stats
// ========================================================================
__global__ void __launch_bounds__(256)
k_stats() {
    const int i = blockIdx.x, b = blockIdx.y, t = threadIdx.x;
    __shared__ float red[8];
    __shared__ float bval;
    const float s1v = g_s1[b * NN + i];
    const float* s2r = g_s2 + b * NN;
    const ull* mrow = g_mask + i * 32;
    float e[8], mk[8];
    float mx = -3e38f;
#pragma unroll
    for (int q = 0; q < 8; ++q) {
        int j = t + q * 256;
        float x = s1v + s2r[j];
        x = fmaxf(x, 0.2f * x);
        ull wd = mrow[j >> 6];
        float f = (float)((wd >> (j & 63)) & 1ull);
        e[q] = x; mk[q] = f;
        mx = fmaxf(mx, f > 0.f ? x : -3e38f);
    }
#pragma unroll
    for (int off = 16; off > 0; off >>= 1)
        mx = fmaxf(mx, __shfl_xor_sync(0xffffffffu, mx, off));
    if ((t & 31) == 0) red[t >> 5] = mx;
    __syncthreads();
    if (t == 0) {
        float v = red[0];
        for (int w2 = 1; w2 < 8; ++w2) v = fmaxf(v, red[w2]);
        bval = v;
    }
    __syncthreads();
    const float M = bval;
    float s = 0.f;
#pragma unroll
    for (int q = 0; q < 8; ++q)
        s += mk[q] * fexp(fminf(fmaxf(e[q] - M, -80.f), 8.f));
#pragma unroll
    for (int off = 16; off > 0; off >>= 1)
        s += __shfl_xor_sync(0xffffffffu, s, off);
    if ((t & 31) == 0) red[t >> 5] = s;
    __syncthreads();
    if (t == 0) {
        float v = 0.f;
        for (int w2 = 0; w2 < 8; ++w2) v += red[w2];
        g_m[b * NN + i] = M;
        g_iz[b * NN + i] = 1.0f / v;
    }
}

// ========================================================================
// Kernel 4: out = elu(P @ Wh), P computed on the fly.
// 128 threads; block tile 64 i-rows x 256 f; j-tile 32.
// Thread tile: 8 rows x 16 f (64 f32x2 accumulators).
// ========================================================================
__global__ void __launch_bounds__(128)
k_attn(float* __restrict__ out) {
    __shared__ __align__(16) float whs[32 * 256];  // 32 KB j-tile of Wh
    __shared__ __align__(16) float ps[32][64];     // 8 KB p tile [jj][row]
    const int b = blockIdx.y, i0 = blockIdx.x * 64;
    const int t = threadIdx.x;
    const int fg = (t >> 1) & 15;
    const int rg = (t & 1) | ((t >> 5) << 1);      // 0..7

    // p-producer mapping: this thread produces p for row prow, 16 jj values
    const int prow = t & 63;
    const int pjq = t >> 6;                        // 0..1
    const float s1r = g_s1[b * NN + i0 + prow];
    const float mr  = g_m [b * NN + i0 + prow];
    const float zr  = g_iz[b * NN + i0 + prow];
    const ull* mrow = g_mask + (size_t)(i0 + prow) * 32;

    ull acc[8][8];
#pragma unroll
    for (int r = 0; r < 8; ++r)
#pragma unroll
        for (int c = 0; c < 8; ++c) acc[r][c] = 0ull;

    const float* whB = g_Wh + (size_t)b * NN * FF;
    const float* s2B = g_s2 + b * NN;

    for (int j0 = 0; j0 < NN; j0 += 32) {
        __syncthreads();
        // Wh tile: 32 rows x 256 f  (2048 float4 / 128 threads)
        const float4* src = (const float4*)(whB + (size_t)j0 * FF);
#pragma unroll
        for (int q = 0; q < 16; ++q)
            ((float4*)whs)[t + q * 128] = src[t + q * 128];

        // p tile: row prow, jj = pjq*16 .. +15 (s2 from global, broadcast LDG)
        {
            ull wd = mrow[j0 >> 6];
#pragma unroll
            for (int q4 = 0; q4 < 4; ++q4) {
                float4 s2v = *(const float4*)&s2B[j0 + pjq * 16 + q4 * 4];
                float sv[4] = {s2v.x, s2v.y, s2v.z, s2v.w};
#pragma unroll
                for (int e = 0; e < 4; ++e) {
                    int jj = pjq * 16 + q4 * 4 + e;
                    float x = s1r + sv[e];
                    x = fmaxf(x, 0.2f * x);
                    float mkf = (float)((wd >> ((j0 + jj) & 63)) & 1ull);
                    ps[jj][prow] = mkf * zr *
                        fexp(fminf(fmaxf(x - mr, -80.f), 8.f));
                }
            }
        }
        __syncthreads();

#pragma unroll 8
        for (int jj = 0; jj < 32; ++jj) {
            const ulonglong2* wrow = (const ulonglong2*)(whs + jj * 256);
            ulonglong2 w0 = wrow[fg];
            ulonglong2 w1 = wrow[fg + 16];
            ulonglong2 w2 = wrow[fg + 32];
            ulonglong2 w3 = wrow[fg + 48];
            float4 pa = *(const float4*)&ps[jj][rg * 8];
            float4 pb = *(const float4*)&ps[jj][rg * 8 + 4];
            float pv[8] = {pa.x, pa.y, pa.z, pa.w, pb.x, pb.y, pb.z, pb.w};
#pragma unroll
            for (int r = 0; r < 8; ++r) {
                ull pp = pk2(pv[r], pv[r]);
                FMA2(acc[r][0], pp, w0.x); FMA2(acc[r][1], pp, w0.y);
                FMA2(acc[r][2], pp, w1.x); FMA2(acc[r][3], pp, w1.y);
                FMA2(acc[r][4], pp, w2.x); FMA2(acc[r][5], pp, w2.y);
                FMA2(acc[r][6], pp, w3.x); FMA2(acc[r][7], pp, w3.y);
            }
        }
    }

    // epilogue: ELU + store (float4, coalesced within fg groups)
    float* ob = out + ((size_t)b * NN + i0 + rg * 8) * FF;
#pragma unroll
    for (int r = 0; r < 8; ++r)
#pragma unroll
        for (int fq = 0; fq < 4; ++fq) {
            float2 lo = upk2(acc[r][2 * fq]);
            float2 hi = upk2(acc[r][2 * fq + 1]);
            float4 v = make_float4(elu1(lo.x), elu1(lo.y),
                                   elu1(hi.x), elu1(hi.y));
            *(float4*)&ob[r * FF + (fq * 16 + fg) * 4] = v;
        }
}

// ========================================================================
extern "C" void kernel_launch(void* const* d_in, const int* in_sizes, int n_in,
                              void* d_out, int out_size) {
    const float* h   = (const float*)d_in[0];
    const int*   adj = (const int*)d_in[1];
    const float* W   = (const float*)d_in[2];
    const float* a   = (const float*)d_in[3];
    float* out = (float*)d_out;

    k_gemm1<<<dim3(NN / 64, BB), 128>>>(h, W, a);
    k_mask <<<NN * 32 / 256, 256>>>(adj);
    k_stats<<<dim3(NN, BB), 256>>>();
    k_attn <<<dim3(NN / 64, BB), 128>>>(out);
}

// round 4
// speedup vs baseline: 1.5218x; 1.0691x over previous
#include <cuda_runtime.h>
#include <cuda_fp16.h>
#include <cstdint>

#define BB 8
#define NN 2048
#define FF 256

// ---- scratch ----
__device__ unsigned short g_WhTh[BB * FF * NN];   // f16 hi, [b][f][j], 8 MB
__device__ unsigned short g_WhTl[BB * FF * NN];   // f16 lo, [b][f][j], 8 MB
__device__ float g_s1[BB * NN];
__device__ float g_s2[BB * NN];
__device__ float g_m[BB * NN];
__device__ float g_iz[BB * NN];
__device__ unsigned long long g_mask[NN * 32];

typedef unsigned long long ull;

// ---- packed f32x2 helpers ----
__device__ __forceinline__ ull pk2(float x, float y) {
    ull r; asm("mov.b64 %0, {%1, %2};" : "=l"(r) : "f"(x), "f"(y)); return r;
}
__device__ __forceinline__ float2 upk2(ull v) {
    float2 r; asm("mov.b64 {%0, %1}, %2;" : "=f"(r.x), "=f"(r.y) : "l"(v)); return r;
}
#define FMA2(d, a, b) asm("fma.rn.f32x2 %0, %1, %2, %0;" : "+l"(d) : "l"(a), "l"(b))

// FFMA-only expf. Valid for x in [-80, 10], rel err ~3e-6.
__device__ __forceinline__ float fexp(float x) {
    const float L2E = 1.4426950408889634f;
    float t = fmaf(x, L2E, 12582912.0f);
    int   k = __float_as_int(t);
    float r = t - 12582912.0f;
    float f = fmaf(x, L2E, -r);
    float p = 1.33335581e-3f;
    p = fmaf(p, f, 9.61812910e-3f);
    p = fmaf(p, f, 5.55041086e-2f);
    p = fmaf(p, f, 2.40226507e-1f);
    p = fmaf(p, f, 6.93147182e-1f);
    p = fmaf(p, f, 1.0f);
    return __int_as_float(__float_as_int(p) + (k << 23));
}
__device__ __forceinline__ float elu1(float x) {
    return x > 0.f ? x : fexp(fmaxf(x, -80.f)) - 1.f;
}

// pack two floats to f16x2, returning residuals
__device__ __forceinline__ uint32_t packh2r(float a, float b, float& ra, float& rb) {
    __half ha = __float2half_rn(a), hb = __float2half_rn(b);
    ra = a - __half2float(ha);
    rb = b - __half2float(hb);
    __half2 h2 = __halves2half2(ha, hb);
    return reinterpret_cast<uint32_t&>(h2);
}
__device__ __forceinline__ uint32_t packh2(float a, float b) {
    __half2 h2 = __floats2half2_rn(a, b);
    return reinterpret_cast<uint32_t&>(h2);
}

#define SWZ128(o) ((o) ^ (((o) >> 3) & 0x70))

// ---- mma.sync / ldmatrix (baseline PTX, works on sm_103 non-'a') ----
__device__ __forceinline__ void ldsm4(uint32_t* r, uint32_t a) {
    asm volatile("ldmatrix.sync.aligned.m8n8.x4.shared.b16 {%0,%1,%2,%3}, [%4];"
        : "=r"(r[0]), "=r"(r[1]), "=r"(r[2]), "=r"(r[3]) : "r"(a));
}
__device__ __forceinline__ void mmaf16(float* c, const uint32_t* a, const uint32_t* b) {
    asm volatile(
        "mma.sync.aligned.m16n8k16.row.col.f32.f16.f16.f32 "
        "{%0,%1,%2,%3}, {%4,%5,%6,%7}, {%8,%9}, {%0,%1,%2,%3};"
        : "+f"(c[0]), "+f"(c[1]), "+f"(c[2]), "+f"(c[3])
        : "r"(a[0]), "r"(a[1]), "r"(a[2]), "r"(a[3]), "r"(b[0]), "r"(b[1]));
}
__device__ __forceinline__ uint32_t smem_u32(const void* p) {
    uint32_t a;
    asm("{ .reg .u64 t; cvta.to.shared.u64 t, %1; cvt.u32.u64 %0, t; }"
        : "=r"(a) : "l"(p));
    return a;
}

// ========================================================================
// Kernel 1: Wh = h @ W; emits f16 hi/lo WhT[b][f][j] + s1/s2.
// ========================================================================
__global__ void __launch_bounds__(128)
k_gemm1(const float* __restrict__ h, const float* __restrict__ W,
        const float* __restrict__ a) {
    __shared__ __align__(16) float Ws[32 * 256];
    __shared__ __align__(16) float hs[32][68];
    __shared__ float as1[256], as2[256];
    const int b = blockIdx.y, i0 = blockIdx.x * 64;
    const int t = threadIdx.x;
    const int fg = (t >> 1) & 15;
    const int rg = (t & 1) | ((t >> 5) << 1);

    as1[t] = a[t];         as1[t + 128] = a[t + 128];
    as2[t] = a[256 + t];   as2[t + 128] = a[384 + t];

    ull acc[8][8];
#pragma unroll
    for (int r = 0; r < 8; ++r)
#pragma unroll
        for (int c = 0; c < 8; ++c) acc[r][c] = 0ull;

    const int lrow = t & 63, kq = t >> 6;
    const float* hrow = h + ((size_t)b * NN + i0 + lrow) * FF;

    for (int k0 = 0; k0 < FF; k0 += 32) {
        __syncthreads();
        const float4* wsrc = (const float4*)(W + (size_t)k0 * FF);
#pragma unroll
        for (int q = 0; q < 16; ++q)
            ((float4*)Ws)[t + q * 128] = wsrc[t + q * 128];
#pragma unroll
        for (int q = 0; q < 4; ++q) {
            float4 hv = *(const float4*)&hrow[k0 + kq * 16 + q * 4];
            hs[kq * 16 + q * 4 + 0][lrow] = hv.x;
            hs[kq * 16 + q * 4 + 1][lrow] = hv.y;
            hs[kq * 16 + q * 4 + 2][lrow] = hv.z;
            hs[kq * 16 + q * 4 + 3][lrow] = hv.w;
        }
        __syncthreads();

#pragma unroll 8
        for (int kk = 0; kk < 32; ++kk) {
            const ulonglong2* wrow = (const ulonglong2*)(Ws + kk * 256);
            ulonglong2 w0 = wrow[fg];
            ulonglong2 w1 = wrow[fg + 16];
            ulonglong2 w2 = wrow[fg + 32];
            ulonglong2 w3 = wrow[fg + 48];
            float4 pa = *(const float4*)&hs[kk][rg * 8];
            float4 pb = *(const float4*)&hs[kk][rg * 8 + 4];
            float pv[8] = {pa.x, pa.y, pa.z, pa.w, pb.x, pb.y, pb.z, pb.w};
#pragma unroll
            for (int r = 0; r < 8; ++r) {
                ull pp = pk2(pv[r], pv[r]);
                FMA2(acc[r][0], pp, w0.x); FMA2(acc[r][1], pp, w0.y);
                FMA2(acc[r][2], pp, w1.x); FMA2(acc[r][3], pp, w1.y);
                FMA2(acc[r][4], pp, w2.x); FMA2(acc[r][5], pp, w2.y);
                FMA2(acc[r][6], pp, w3.x); FMA2(acc[r][7], pp, w3.y);
            }
        }
    }

    // epilogue: s1/s2 partials + transposed f16 hi/lo stores
    float p1[8], p2[8];
#pragma unroll
    for (int r = 0; r < 8; ++r) { p1[r] = 0.f; p2[r] = 0.f; }

    const size_t jbase = (size_t)i0 + rg * 8;
#pragma unroll
    for (int fq = 0; fq < 4; ++fq) {
        int c = (fq * 16 + fg) * 4;
#pragma unroll
        for (int e = 0; e < 4; ++e) {
            int f = c + e;
            float a1v = as1[f], a2v = as2[f];
            float col[8];
#pragma unroll
            for (int r = 0; r < 8; ++r) {
                float2 v2 = upk2(acc[r][2 * fq + (e >> 1)]);
                float v = (e & 1) ? v2.y : v2.x;
                col[r] = v;
                p1[r] += v * a1v;
                p2[r] += v * a2v;
            }
            uint32_t hi[4], lo[4];
#pragma unroll
            for (int q = 0; q < 4; ++q) {
                float r0, r1;
                hi[q] = packh2r(col[2 * q], col[2 * q + 1], r0, r1);
                lo[q] = packh2(r0, r1);
            }
            size_t off = ((size_t)(b * FF + f)) * NN + jbase;
            *(uint4*)(g_WhTh + off) = make_uint4(hi[0], hi[1], hi[2], hi[3]);
            *(uint4*)(g_WhTl + off) = make_uint4(lo[0], lo[1], lo[2], lo[3]);
        }
    }
#pragma unroll
    for (int off2 = 2; off2 <= 16; off2 <<= 1)
#pragma unroll
        for (int r = 0; r < 8; ++r) {
            p1[r] += __shfl_xor_sync(0xffffffffu, p1[r], off2);
            p2[r] += __shfl_xor_sync(0xffffffffu, p2[r], off2);
        }
    if (fg == 0) {
#pragma unroll
        for (int r = 0; r < 8; ++r) {
            g_s1[b * NN + i0 + rg * 8 + r] = p1[r];
            g_s2[b * NN + i0 + rg * 8 + r] = p2[r];
        }
    }
}

// ========================================================================
// Kernel 2: pack mask bits
// ========================================================================
__global__ void k_mask(const int* __restrict__ adj) {
    int idx = blockIdx.x * 256 + threadIdx.x;
    int i = idx >> 5, w = idx & 31;
    const int* row = adj + (size_t)i * NN + w * 64;
    ull m = 0ull;
#pragma unroll 8
    for (int bb = 0; bb < 64; ++bb)
        if (row[bb] > 0) m |= 1ull << bb;
    int d = i - w * 64;
    if (d >= 0 && d < 64) m |= 1ull << d;
    g_mask[idx] = m;
}

// ========================================================================
// Kernel 3: per-row softmax stats
// ========================================================================
__global__ void __launch_bounds__(256)
k_stats() {
    const int i = blockIdx.x, b = blockIdx.y, t = threadIdx.x;
    __shared__ float red[8];
    __shared__ float bval;
    const float s1v = g_s1[b * NN + i];
    const float* s2r = g_s2 + b * NN;
    const ull* mrow = g_mask + i * 32;
    float e[8], mk[8];
    float mx = -3e38f;
#pragma unroll
    for (int q = 0; q < 8; ++q) {
        int j = t + q * 256;
        float x = s1v + s2r[j];
        x = fmaxf(x, 0.2f * x);
        ull wd = mrow[j >> 6];
        float f = (float)((wd >> (j & 63)) & 1ull);
        e[q] = x; mk[q] = f;
        mx = fmaxf(mx, f > 0.f ? x : -3e38f);
    }
#pragma unroll
    for (int off = 16; off > 0; off >>= 1)
        mx = fmaxf(mx, __shfl_xor_sync(0xffffffffu, mx, off));
    if ((t & 31) == 0) red[t >> 5] = mx;
    __syncthreads();
    if (t == 0) {
        float v = red[0];
        for (int w2 = 1; w2 < 8; ++w2) v = fmaxf(v, red[w2]);
        bval = v;
    }
    __syncthreads();
    const float M = bval;
    float s = 0.f;
#pragma unroll
    for (int q = 0; q < 8; ++q)
        s += mk[q] * fexp(fminf(fmaxf(e[q] - M, -80.f), 8.f));
#pragma unroll
    for (int off = 16; off > 0; off >>= 1)
        s += __shfl_xor_sync(0xffffffffu, s, off);
    if ((t & 31) == 0) red[t >> 5] = s;
    __syncthreads();
    if (t == 0) {
        float v = 0.f;
        for (int w2 = 0; w2 < 8; ++w2) v += red[w2];
        g_m[b * NN + i] = M;
        g_iz[b * NN + i] = 1.0f / v;
    }
}

// ========================================================================
// Kernel 4 (mma.sync f16): out = elu(P @ Wh), 3-term f16 split.
// Grid (16 m-tiles, 2 f-tiles, 8 b); 256 thr = 8 warps (4m x 2n).
// CTA tile M=128 x N=128; warp tile m32 x n64; K=2048 in 32 chunks of 64.
// Smem (dynamic 64KB): Ph, Pl [128][64] f16 + Bh, Bl [128f][64j] f16 (SW128).
// ========================================================================
#define O_PH 0
#define O_PL 16384
#define O_BH 32768
#define O_BL 49152

__global__ void __launch_bounds__(256, 2)
k_attn(float* __restrict__ out) {
    extern __shared__ __align__(1024) char sm[];
    const uint32_t smb = smem_u32(sm);
    const int bz = blockIdx.z, i0 = blockIdx.x * 128, fy = blockIdx.y;
    const int t = threadIdx.x, wid = t >> 5, lane = t & 31;
    const int wm = wid & 3, wn = wid >> 2;

    // P-producer mapping: row prow (0..127), j-half jq (32 j's)
    const int prow = t >> 1, jq = t & 1;
    const float s1r = g_s1[bz * NN + i0 + prow];
    const float mr  = g_m [bz * NN + i0 + prow];
    const float zr  = g_iz[bz * NN + i0 + prow];
    const ull* mrow = g_mask + (size_t)(i0 + prow) * 32;

    const unsigned short* whH = g_WhTh + ((size_t)bz * FF + fy * 128) * NN;
    const unsigned short* whL = g_WhTl + ((size_t)bz * FF + fy * 128) * NN;
    const float* s2B = g_s2 + bz * NN;

    // ldmatrix lane address components
    const uint32_t a_l = (uint32_t)(((wm * 32 + (lane & 15)) << 7) | ((lane >> 4) << 4));
    const uint32_t b_l = (uint32_t)(((wn * 64 + ((lane >> 4) << 3) + (lane & 7)) << 7)
                                    | (((lane >> 3) & 1) << 4));

    float acc[2][8][4];
#pragma unroll
    for (int mt = 0; mt < 2; ++mt)
#pragma unroll
        for (int nt = 0; nt < 8; ++nt)
#pragma unroll
            for (int e = 0; e < 4; ++e) acc[mt][nt][e] = 0.f;

    for (int c = 0; c < 32; ++c) {
        const int j0 = c * 64;
        __syncthreads();   // previous chunk's mma reads done

        // ---- produce P tile (f16 hi/lo) ----
        {
            ull wd = mrow[j0 >> 6];
            const float* s2p = s2B + j0 + jq * 32;
            uint32_t base = (uint32_t)(prow * 128 + jq * 64);
#pragma unroll
            for (int g = 0; g < 8; ++g) {
                float4 s2v = *(const float4*)(s2p + g * 4);
                float sv[4] = {s2v.x, s2v.y, s2v.z, s2v.w};
                float p[4];
#pragma unroll
                for (int e = 0; e < 4; ++e) {
                    int jl = jq * 32 + g * 4 + e;
                    float x = s1r + sv[e];
                    x = fmaxf(x, 0.2f * x);
                    float mkf = (float)((wd >> jl) & 1ull);
                    p[e] = mkf * zr * fexp(fminf(fmaxf(x - mr, -80.f), 8.f));
                }
                float r0, r1, r2, r3;
                uint32_t h01 = packh2r(p[0], p[1], r0, r1);
                uint32_t h23 = packh2r(p[2], p[3], r2, r3);
                uint32_t l01 = packh2(r0, r1);
                uint32_t l23 = packh2(r2, r3);
                uint32_t o = SWZ128(base + g * 8);
                *(uint2*)(sm + O_PH + o) = make_uint2(h01, h23);
                *(uint2*)(sm + O_PL + o) = make_uint2(l01, l23);
            }
        }
        // ---- load B tiles (WhT chunk, 128 f x 64 j) ----
#pragma unroll
        for (int q = 0; q < 4; ++q) {
            int idx = t + q * 256;               // 0..1023
            int f = idx >> 3, seg = idx & 7;
            size_t goff = (size_t)f * NN + j0 + seg * 8;
            uint32_t soff = SWZ128((uint32_t)(f * 128 + seg * 16));
            *(uint4*)(sm + O_BH + soff) = *(const uint4*)(whH + goff);
            *(uint4*)(sm + O_BL + soff) = *(const uint4*)(whL + goff);
        }
        __syncthreads();

        // ---- mma: 4 ksteps x (3 combos) ----
#pragma unroll
        for (int k16 = 0; k16 < 4; ++k16) {
            uint32_t ah[2][4], al[2][4];
#pragma unroll
            for (int mt = 0; mt < 2; ++mt) {
                uint32_t ao = a_l + (uint32_t)(mt * 2048 + k16 * 32);
                ldsm4(ah[mt], smb + O_PH + SWZ128(ao));
                ldsm4(al[mt], smb + O_PL + SWZ128(ao));
            }
#pragma unroll
            for (int nt2 = 0; nt2 < 4; ++nt2) {
                uint32_t bo = b_l + (uint32_t)(nt2 * 2048 + k16 * 32);
                uint32_t bh[4], bl[4];
                ldsm4(bh, smb + O_BH + SWZ128(bo));
                ldsm4(bl, smb + O_BL + SWZ128(bo));
#pragma unroll
                for (int mt = 0; mt < 2; ++mt) {
                    mmaf16(acc[mt][nt2 * 2 + 0], ah[mt], bh);
                    mmaf16(acc[mt][nt2 * 2 + 1], ah[mt], bh + 2);
                    mmaf16(acc[mt][nt2 * 2 + 0], ah[mt], bl);
                    mmaf16(acc[mt][nt2 * 2 + 1], ah[mt], bl + 2);
                    mmaf16(acc[mt][nt2 * 2 + 0], al[mt], bh);
                    mmaf16(acc[mt][nt2 * 2 + 1], al[mt], bh + 2);
                }
            }
        }
    }

    // ---- epilogue: ELU + store ----
    const int tq = lane >> 2, tr = lane & 3;
#pragma unroll
    for (int mt = 0; mt < 2; ++mt) {
        int i = i0 + wm * 32 + mt * 16 + tq;
        float* op0 = out + ((size_t)bz * NN + i) * FF + fy * 128 + wn * 64 + tr * 2;
#pragma unroll
        for (int nt = 0; nt < 8; ++nt) {
            float2 v0 = make_float2(elu1(acc[mt][nt][0]), elu1(acc[mt][nt][1]));
            float2 v1 = make_float2(elu1(acc[mt][nt][2]), elu1(acc[mt][nt][3]));
            *(float2*)(op0 + nt * 8) = v0;
            *(float2*)(op0 + nt * 8 + 8 * FF) = v1;
        }
    }
}

// ========================================================================
extern "C" void kernel_launch(void* const* d_in, const int* in_sizes, int n_in,
                              void* d_out, int out_size) {
    const float* h   = (const float*)d_in[0];
    const int*   adj = (const int*)d_in[1];
    const float* W   = (const float*)d_in[2];
    const float* a   = (const float*)d_in[3];
    float* out = (float*)d_out;

    cudaFuncSetAttribute(k_attn, cudaFuncAttributeMaxDynamicSharedMemorySize, 65536);

    k_gemm1<<<dim3(NN / 64, BB), 128>>>(h, W, a);
    k_mask <<<NN * 32 / 256, 256>>>(adj);
    k_stats<<<dim3(NN, BB), 256>>>();
    k_attn <<<dim3(16, 2, 8), 256, 65536>>>(out);
}

// round 5
// speedup vs baseline: 2.5548x; 1.6788x over previous
#include <cuda_runtime.h>
#include <cuda_fp16.h>
#include <cstdint>

#define BB 8
#define NN 2048
#define FF 256

// ---- scratch ----
__device__ unsigned short g_WhTh[BB * FF * NN];   // f16 hi, [b][f][j], 8 MB
__device__ unsigned short g_WhTl[BB * FF * NN];   // f16 lo, [b][f][j], 8 MB
__device__ float g_s1[BB * NN];
__device__ float g_s2[BB * NN];
__device__ float g_m[BB * NN];
__device__ float g_iz[BB * NN];
__device__ unsigned long long g_mask[NN * 32];

typedef unsigned long long ull;

// ---- packed f32x2 helpers ----
__device__ __forceinline__ ull pk2(float x, float y) {
    ull r; asm("mov.b64 %0, {%1, %2};" : "=l"(r) : "f"(x), "f"(y)); return r;
}
__device__ __forceinline__ float2 upk2(ull v) {
    float2 r; asm("mov.b64 {%0, %1}, %2;" : "=f"(r.x), "=f"(r.y) : "l"(v)); return r;
}
#define FMA2(d, a, b) asm("fma.rn.f32x2 %0, %1, %2, %0;" : "+l"(d) : "l"(a), "l"(b))

// FFMA-only expf. Valid for x in [-80, 10], rel err ~3e-6.
__device__ __forceinline__ float fexp(float x) {
    const float L2E = 1.4426950408889634f;
    float t = fmaf(x, L2E, 12582912.0f);
    int   k = __float_as_int(t);
    float r = t - 12582912.0f;
    float f = fmaf(x, L2E, -r);
    float p = 1.33335581e-3f;
    p = fmaf(p, f, 9.61812910e-3f);
    p = fmaf(p, f, 5.55041086e-2f);
    p = fmaf(p, f, 2.40226507e-1f);
    p = fmaf(p, f, 6.93147182e-1f);
    p = fmaf(p, f, 1.0f);
    return __int_as_float(__float_as_int(p) + (k << 23));
}
__device__ __forceinline__ float elu1(float x) {
    return x > 0.f ? x : fexp(fmaxf(x, -80.f)) - 1.f;
}

// pack two floats to f16x2, returning residuals
__device__ __forceinline__ uint32_t packh2r(float a, float b, float& ra, float& rb) {
    __half ha = __float2half_rn(a), hb = __float2half_rn(b);
    ra = a - __half2float(ha);
    rb = b - __half2float(hb);
    __half2 h2 = __halves2half2(ha, hb);
    return reinterpret_cast<uint32_t&>(h2);
}
__device__ __forceinline__ uint32_t packh2(float a, float b) {
    __half2 h2 = __floats2half2_rn(a, b);
    return reinterpret_cast<uint32_t&>(h2);
}

#define SWZ128(o) ((o) ^ (((o) >> 3) & 0x70))

// ---- mma.sync / ldmatrix / cp.async (baseline PTX, sm_103-safe) ----
__device__ __forceinline__ void ldsm4(uint32_t* r, uint32_t a) {
    asm volatile("ldmatrix.sync.aligned.m8n8.x4.shared.b16 {%0,%1,%2,%3}, [%4];"
        : "=r"(r[0]), "=r"(r[1]), "=r"(r[2]), "=r"(r[3]) : "r"(a));
}
__device__ __forceinline__ void mmaf16(float* c, const uint32_t* a, const uint32_t* b) {
    asm volatile(
        "mma.sync.aligned.m16n8k16.row.col.f32.f16.f16.f32 "
        "{%0,%1,%2,%3}, {%4,%5,%6,%7}, {%8,%9}, {%0,%1,%2,%3};"
        : "+f"(c[0]), "+f"(c[1]), "+f"(c[2]), "+f"(c[3])
        : "r"(a[0]), "r"(a[1]), "r"(a[2]), "r"(a[3]), "r"(b[0]), "r"(b[1]));
}
__device__ __forceinline__ uint32_t smem_u32(const void* p) {
    uint32_t a;
    asm("{ .reg .u64 t; cvta.to.shared.u64 t, %1; cvt.u32.u64 %0, t; }"
        : "=r"(a) : "l"(p));
    return a;
}
#define CPA16(dst, src) asm volatile( \
    "cp.async.cg.shared.global [%0], [%1], 16;" :: "r"(dst), "l"(src))
#define CPCOMMIT() asm volatile("cp.async.commit_group;" ::: "memory")
#define CPWAIT1() asm volatile("cp.async.wait_group 1;" ::: "memory")
#define CPWAIT0() asm volatile("cp.async.wait_group 0;" ::: "memory")

// ========================================================================
// Kernel 1: Wh = h @ W; emits f16 hi/lo WhT[b][f][j] + s1/s2.
// ========================================================================
__global__ void __launch_bounds__(128)
k_gemm1(const float* __restrict__ h, const float* __restrict__ W,
        const float* __restrict__ a) {
    __shared__ __align__(16) float Ws[32 * 256];
    __shared__ __align__(16) float hs[32][68];
    __shared__ float as1[256], as2[256];
    const int b = blockIdx.y, i0 = blockIdx.x * 64;
    const int t = threadIdx.x;
    const int fg = (t >> 1) & 15;
    const int rg = (t & 1) | ((t >> 5) << 1);

    as1[t] = a[t];         as1[t + 128] = a[t + 128];
    as2[t] = a[256 + t];   as2[t + 128] = a[384 + t];

    ull acc[8][8];
#pragma unroll
    for (int r = 0; r < 8; ++r)
#pragma unroll
        for (int c = 0; c < 8; ++c) acc[r][c] = 0ull;

    const int lrow = t & 63, kq = t >> 6;
    const float* hrow = h + ((size_t)b * NN + i0 + lrow) * FF;

    for (int k0 = 0; k0 < FF; k0 += 32) {
        __syncthreads();
        const float4* wsrc = (const float4*)(W + (size_t)k0 * FF);
#pragma unroll
        for (int q = 0; q < 16; ++q)
            ((float4*)Ws)[t + q * 128] = wsrc[t + q * 128];
#pragma unroll
        for (int q = 0; q < 4; ++q) {
            float4 hv = *(const float4*)&hrow[k0 + kq * 16 + q * 4];
            hs[kq * 16 + q * 4 + 0][lrow] = hv.x;
            hs[kq * 16 + q * 4 + 1][lrow] = hv.y;
            hs[kq * 16 + q * 4 + 2][lrow] = hv.z;
            hs[kq * 16 + q * 4 + 3][lrow] = hv.w;
        }
        __syncthreads();

#pragma unroll 8
        for (int kk = 0; kk < 32; ++kk) {
            const ulonglong2* wrow = (const ulonglong2*)(Ws + kk * 256);
            ulonglong2 w0 = wrow[fg];
            ulonglong2 w1 = wrow[fg + 16];
            ulonglong2 w2 = wrow[fg + 32];
            ulonglong2 w3 = wrow[fg + 48];
            float4 pa = *(const float4*)&hs[kk][rg * 8];
            float4 pb = *(const float4*)&hs[kk][rg * 8 + 4];
            float pv[8] = {pa.x, pa.y, pa.z, pa.w, pb.x, pb.y, pb.z, pb.w};
#pragma unroll
            for (int r = 0; r < 8; ++r) {
                ull pp = pk2(pv[r], pv[r]);
                FMA2(acc[r][0], pp, w0.x); FMA2(acc[r][1], pp, w0.y);
                FMA2(acc[r][2], pp, w1.x); FMA2(acc[r][3], pp, w1.y);
                FMA2(acc[r][4], pp, w2.x); FMA2(acc[r][5], pp, w2.y);
                FMA2(acc[r][6], pp, w3.x); FMA2(acc[r][7], pp, w3.y);
            }
        }
    }

    float p1[8], p2[8];
#pragma unroll
    for (int r = 0; r < 8; ++r) { p1[r] = 0.f; p2[r] = 0.f; }

    const size_t jbase = (size_t)i0 + rg * 8;
#pragma unroll
    for (int fq = 0; fq < 4; ++fq) {
        int c = (fq * 16 + fg) * 4;
#pragma unroll
        for (int e = 0; e < 4; ++e) {
            int f = c + e;
            float a1v = as1[f], a2v = as2[f];
            float col[8];
#pragma unroll
            for (int r = 0; r < 8; ++r) {
                float2 v2 = upk2(acc[r][2 * fq + (e >> 1)]);
                float v = (e & 1) ? v2.y : v2.x;
                col[r] = v;
                p1[r] += v * a1v;
                p2[r] += v * a2v;
            }
            uint32_t hi[4], lo[4];
#pragma unroll
            for (int q = 0; q < 4; ++q) {
                float r0, r1;
                hi[q] = packh2r(col[2 * q], col[2 * q + 1], r0, r1);
                lo[q] = packh2(r0, r1);
            }
            size_t off = ((size_t)(b * FF + f)) * NN + jbase;
            *(uint4*)(g_WhTh + off) = make_uint4(hi[0], hi[1], hi[2], hi[3]);
            *(uint4*)(g_WhTl + off) = make_uint4(lo[0], lo[1], lo[2], lo[3]);
        }
    }
#pragma unroll
    for (int off2 = 2; off2 <= 16; off2 <<= 1)
#pragma unroll
        for (int r = 0; r < 8; ++r) {
            p1[r] += __shfl_xor_sync(0xffffffffu, p1[r], off2);
            p2[r] += __shfl_xor_sync(0xffffffffu, p2[r], off2);
        }
    if (fg == 0) {
#pragma unroll
        for (int r = 0; r < 8; ++r) {
            g_s1[b * NN + i0 + rg * 8 + r] = p1[r];
            g_s2[b * NN + i0 + rg * 8 + r] = p2[r];
        }
    }
}

// ========================================================================
// Kernel 2: pack mask bits
// ========================================================================
__global__ void k_mask(const int* __restrict__ adj) {
    int idx = blockIdx.x * 256 + threadIdx.x;
    int i = idx >> 5, w = idx & 31;
    const int* row = adj + (size_t)i * NN + w * 64;
    ull m = 0ull;
#pragma unroll 8
    for (int bb = 0; bb < 64; ++bb)
        if (row[bb] > 0) m |= 1ull << bb;
    int d = i - w * 64;
    if (d >= 0 && d < 64) m |= 1ull << d;
    g_mask[idx] = m;
}

// ========================================================================
// Kernel 3: per-row softmax stats
// ========================================================================
__global__ void __launch_bounds__(256)
k_stats() {
    const int i = blockIdx.x, b = blockIdx.y, t = threadIdx.x;
    __shared__ float red[8];
    __shared__ float bval;
    const float s1v = g_s1[b * NN + i];
    const float* s2r = g_s2 + b * NN;
    const ull* mrow = g_mask + i * 32;
    float e[8], mk[8];
    float mx = -3e38f;
#pragma unroll
    for (int q = 0; q < 8; ++q) {
        int j = t + q * 256;
        float x = s1v + s2r[j];
        x = fmaxf(x, 0.2f * x);
        ull wd = mrow[j >> 6];
        float f = (float)((wd >> (j & 63)) & 1ull);
        e[q] = x; mk[q] = f;
        mx = fmaxf(mx, f > 0.f ? x : -3e38f);
    }
#pragma unroll
    for (int off = 16; off > 0; off >>= 1)
        mx = fmaxf(mx, __shfl_xor_sync(0xffffffffu, mx, off));
    if ((t & 31) == 0) red[t >> 5] = mx;
    __syncthreads();
    if (t == 0) {
        float v = red[0];
        for (int w2 = 1; w2 < 8; ++w2) v = fmaxf(v, red[w2]);
        bval = v;
    }
    __syncthreads();
    const float M = bval;
    float s = 0.f;
#pragma unroll
    for (int q = 0; q < 8; ++q)
        s += mk[q] * fexp(fminf(fmaxf(e[q] - M, -80.f), 8.f));
#pragma unroll
    for (int off = 16; off > 0; off >>= 1)
        s += __shfl_xor_sync(0xffffffffu, s, off);
    if ((t & 31) == 0) red[t >> 5] = s;
    __syncthreads();
    if (t == 0) {
        float v = 0.f;
        for (int w2 = 0; w2 < 8; ++w2) v += red[w2];
        g_m[b * NN + i] = M;
        g_iz[b * NN + i] = 1.0f / v;
    }
}

// ========================================================================
// Kernel 4 (mma.sync f16): out = elu(P @ Wh), 2-term (Ph*Whh + Ph*Whl).
// Grid (16 m, 2 f, 8 b); 256 thr = 8 warps (4m x 2n); warp m32 x n64.
// K=2048 in 32 chunks of 64; cp.async double-buffered smem pipeline.
// Per-buffer: Ph[128][64] + Bh[128][64] + Bl[128][64] f16 SW128 = 48 KB.
// ========================================================================
#define BUFSZ 49152
#define O_PH 0
#define O_BH 16384
#define O_BL 32768

__global__ void __launch_bounds__(256, 2)
k_attn(float* __restrict__ out) {
    extern __shared__ __align__(1024) char sm[];
    const uint32_t smb = smem_u32(sm);
    const int bz = blockIdx.z, i0 = blockIdx.x * 128, fy = blockIdx.y;
    const int t = threadIdx.x, wid = t >> 5, lane = t & 31;
    const int wm = wid & 3, wn = wid >> 2;

    const int prow = t >> 1, jq = t & 1;
    const float s1r = g_s1[bz * NN + i0 + prow];
    const float mr  = g_m [bz * NN + i0 + prow];
    const float zr  = g_iz[bz * NN + i0 + prow];
    const ull* mrow = g_mask + (size_t)(i0 + prow) * 32;

    const unsigned short* whH = g_WhTh + ((size_t)bz * FF + fy * 128) * NN;
    const unsigned short* whL = g_WhTl + ((size_t)bz * FF + fy * 128) * NN;
    const float* s2B = g_s2 + bz * NN;

    const uint32_t a_l = (uint32_t)(((wm * 32 + (lane & 15)) << 7) | ((lane >> 4) << 4));
    const uint32_t b_l = (uint32_t)(((wn * 64 + ((lane >> 4) << 3) + (lane & 7)) << 7)
                                    | (((lane >> 3) & 1) << 4));

    float acc[2][8][4];
#pragma unroll
    for (int mt = 0; mt < 2; ++mt)
#pragma unroll
        for (int nt = 0; nt < 8; ++nt)
#pragma unroll
            for (int e = 0; e < 4; ++e) acc[mt][nt][e] = 0.f;

    // ---- staging lambdas ----
    auto stageB = [&](int c, uint32_t bufa) {
        const int j0 = c * 64;
#pragma unroll
        for (int q = 0; q < 4; ++q) {
            int idx = t + q * 256;               // 0..1023
            int f = idx >> 3, seg = idx & 7;
            size_t goff = (size_t)f * NN + j0 + seg * 8;
            uint32_t soff = SWZ128((uint32_t)(f * 128 + seg * 16));
            CPA16(bufa + O_BH + soff, whH + goff);
            CPA16(bufa + O_BL + soff, whL + goff);
        }
    };
    auto stageP = [&](int c, char* buf) {
        const int j0 = c * 64;
        ull wd = mrow[j0 >> 6];
        const float* s2p = s2B + j0 + jq * 32;
        uint32_t base = (uint32_t)(prow * 128 + jq * 64);
#pragma unroll
        for (int g = 0; g < 8; ++g) {
            float4 s2v = *(const float4*)(s2p + g * 4);
            float sv[4] = {s2v.x, s2v.y, s2v.z, s2v.w};
            float p[4];
#pragma unroll
            for (int e = 0; e < 4; ++e) {
                int jl = jq * 32 + g * 4 + e;
                float x = s1r + sv[e];
                x = fmaxf(x, 0.2f * x);
                float mkf = (float)((wd >> jl) & 1ull);
                p[e] = mkf * zr * fexp(fminf(fmaxf(x - mr, -80.f), 8.f));
            }
            uint32_t h01 = packh2(p[0], p[1]);
            uint32_t h23 = packh2(p[2], p[3]);
            *(uint2*)(buf + O_PH + SWZ128(base + g * 8)) = make_uint2(h01, h23);
        }
    };

    // ---- prologue: stage chunk 0 into buffer 0 ----
    stageB(0, smb);
    CPCOMMIT();
    stageP(0, sm);

    for (int c = 0; c < 32; ++c) {
        const int p = c & 1;
        const uint32_t bufa = smb + p * BUFSZ;
        char* bufn = sm + (p ^ 1) * BUFSZ;

        if (c < 31) {
            stageB(c + 1, smb + (p ^ 1) * BUFSZ);
            CPCOMMIT();
            stageP(c + 1, bufn);
            CPWAIT1();
        } else {
            CPWAIT0();
        }
        __syncthreads();

        // ---- mma over buffer p ----
#pragma unroll
        for (int k16 = 0; k16 < 4; ++k16) {
            uint32_t ah[2][4];
#pragma unroll
            for (int mt = 0; mt < 2; ++mt)
                ldsm4(ah[mt], bufa + O_PH +
                      SWZ128(a_l + (uint32_t)(mt * 2048 + k16 * 32)));
#pragma unroll
            for (int nt2 = 0; nt2 < 4; ++nt2) {
                uint32_t bo = SWZ128(b_l + (uint32_t)(nt2 * 2048 + k16 * 32));
                uint32_t bh[4], bl[4];
                ldsm4(bh, bufa + O_BH + bo);
                ldsm4(bl, bufa + O_BL + bo);
#pragma unroll
                for (int mt = 0; mt < 2; ++mt) {
                    mmaf16(acc[mt][nt2 * 2 + 0], ah[mt], bh);
                    mmaf16(acc[mt][nt2 * 2 + 1], ah[mt], bh + 2);
                    mmaf16(acc[mt][nt2 * 2 + 0], ah[mt], bl);
                    mmaf16(acc[mt][nt2 * 2 + 1], ah[mt], bl + 2);
                }
            }
        }
        __syncthreads();
    }

    // ---- epilogue: ELU + store ----
    const int tq = lane >> 2, tr = lane & 3;
#pragma unroll
    for (int mt = 0; mt < 2; ++mt) {
        int i = i0 + wm * 32 + mt * 16 + tq;
        float* op0 = out + ((size_t)bz * NN + i) * FF + fy * 128 + wn * 64 + tr * 2;
#pragma unroll
        for (int nt = 0; nt < 8; ++nt) {
            float2 v0 = make_float2(elu1(acc[mt][nt][0]), elu1(acc[mt][nt][1]));
            float2 v1 = make_float2(elu1(acc[mt][nt][2]), elu1(acc[mt][nt][3]));
            *(float2*)(op0 + nt * 8) = v0;
            *(float2*)(op0 + nt * 8 + 8 * FF) = v1;
        }
    }
}

// ========================================================================
extern "C" void kernel_launch(void* const* d_in, const int* in_sizes, int n_in,
                              void* d_out, int out_size) {
    const float* h   = (const float*)d_in[0];
    const int*   adj = (const int*)d_in[1];
    const float* W   = (const float*)d_in[2];
    const float* a   = (const float*)d_in[3];
    float* out = (float*)d_out;

    cudaFuncSetAttribute(k_attn, cudaFuncAttributeMaxDynamicSharedMemorySize,
                         2 * BUFSZ);

    k_gemm1<<<dim3(NN / 64, BB), 128>>>(h, W, a);
    k_mask <<<NN * 32 / 256, 256>>>(adj);
    k_stats<<<dim3(NN, BB), 256>>>();
    k_attn <<<dim3(16, 2, 8), 256, 2 * BUFSZ>>>(out);
}

// round 6
// speedup vs baseline: 2.7632x; 1.0816x over previous
#include <cuda_runtime.h>
#include <cuda_fp16.h>
#include <cstdint>

#define BB 8
#define NN 2048
#define FF 256

// ---- scratch ----
__device__ unsigned short g_WhTh[BB * FF * NN];   // f16 hi, [b][f][j], 8 MB
__device__ unsigned short g_WtH[FF * FF];         // f16 W^T hi [fout][fin]
__device__ unsigned short g_WtL[FF * FF];         // f16 W^T lo
__device__ float g_s1[BB * NN];
__device__ float g_s2[BB * NN];
__device__ float g_m[BB * NN];
__device__ float g_iz[BB * NN];
__device__ unsigned long long g_mask[NN * 32];

typedef unsigned long long ull;

// FFMA-only expf. Valid for x in [-80, 10], rel err ~3e-6.
__device__ __forceinline__ float fexp(float x) {
    const float L2E = 1.4426950408889634f;
    float t = fmaf(x, L2E, 12582912.0f);
    int   k = __float_as_int(t);
    float r = t - 12582912.0f;
    float f = fmaf(x, L2E, -r);
    float p = 1.33335581e-3f;
    p = fmaf(p, f, 9.61812910e-3f);
    p = fmaf(p, f, 5.55041086e-2f);
    p = fmaf(p, f, 2.40226507e-1f);
    p = fmaf(p, f, 6.93147182e-1f);
    p = fmaf(p, f, 1.0f);
    return __int_as_float(__float_as_int(p) + (k << 23));
}
__device__ __forceinline__ float elu1(float x) {
    return x > 0.f ? x : fexp(fmaxf(x, -80.f)) - 1.f;
}
__device__ __forceinline__ uint32_t packh2r(float a, float b, float& ra, float& rb) {
    __half ha = __float2half_rn(a), hb = __float2half_rn(b);
    ra = a - __half2float(ha);
    rb = b - __half2float(hb);
    __half2 h2 = __halves2half2(ha, hb);
    return reinterpret_cast<uint32_t&>(h2);
}
__device__ __forceinline__ uint32_t packh2(float a, float b) {
    __half2 h2 = __floats2half2_rn(a, b);
    return reinterpret_cast<uint32_t&>(h2);
}

#define SWZ128(o) ((o) ^ (((o) >> 3) & 0x70))

// ---- mma.sync / ldmatrix / cp.async ----
__device__ __forceinline__ void ldsm4(uint32_t* r, uint32_t a) {
    asm volatile("ldmatrix.sync.aligned.m8n8.x4.shared.b16 {%0,%1,%2,%3}, [%4];"
        : "=r"(r[0]), "=r"(r[1]), "=r"(r[2]), "=r"(r[3]) : "r"(a));
}
__device__ __forceinline__ void mmaf16(float* c, const uint32_t* a, const uint32_t* b) {
    asm volatile(
        "mma.sync.aligned.m16n8k16.row.col.f32.f16.f16.f32 "
        "{%0,%1,%2,%3}, {%4,%5,%6,%7}, {%8,%9}, {%0,%1,%2,%3};"
        : "+f"(c[0]), "+f"(c[1]), "+f"(c[2]), "+f"(c[3])
        : "r"(a[0]), "r"(a[1]), "r"(a[2]), "r"(a[3]), "r"(b[0]), "r"(b[1]));
}
__device__ __forceinline__ uint32_t smem_u32(const void* p) {
    uint32_t a;
    asm("{ .reg .u64 t; cvta.to.shared.u64 t, %1; cvt.u32.u64 %0, t; }"
        : "=r"(a) : "l"(p));
    return a;
}
#define CPA16(dst, src) asm volatile( \
    "cp.async.cg.shared.global [%0], [%1], 16;" :: "r"(dst), "l"(src))
#define CPCOMMIT() asm volatile("cp.async.commit_group;" ::: "memory")
#define CPWAIT1() asm volatile("cp.async.wait_group 1;" ::: "memory")
#define CPWAIT0() asm volatile("cp.async.wait_group 0;" ::: "memory")

// ========================================================================
// Kernel 0: pack W -> f16 hi/lo, transposed [fout][fin]
// ========================================================================
__global__ void k_packW(const float* __restrict__ W) {
    const int fo = blockIdx.x, fi = threadIdx.x;   // 256 x 256
    float v = W[fi * FF + fo];
    float r0, dummy;
    uint32_t hp = packh2r(v, 0.f, r0, dummy);
    g_WtH[fo * FF + fi] = (unsigned short)(hp & 0xffff);
    g_WtL[fo * FF + fi] = (unsigned short)(packh2(r0, 0.f) & 0xffff);
}

// ========================================================================
// Kernel 1: pack mask bits + zero s1/s2 (for gemm1 atomics)
// ========================================================================
__global__ void k_mask(const int* __restrict__ adj) {
    int idx = blockIdx.x * 256 + threadIdx.x;   // 0..65535
    if (idx < BB * NN) { g_s1[idx] = 0.f; g_s2[idx] = 0.f; }
    int i = idx >> 5, w = idx & 31;
    const int* row = adj + (size_t)i * NN + w * 64;
    ull m = 0ull;
#pragma unroll 8
    for (int bb = 0; bb < 64; ++bb)
        if (row[bb] > 0) m |= 1ull << bb;
    int d = i - w * 64;
    if (d >= 0 && d < 64) m |= 1ull << d;
    g_mask[idx] = m;
}

// ========================================================================
// Kernel 2 (mma): Wh = h @ W (3-term f16 split, fp32-accurate).
// Emits WhT-hi f16 [b][f][j] + s1/s2 (fp32, atomicAdd partials).
// Grid (128, 2): 128 i-rows x 128 f per CTA, K=256 in 4 chunks of 64.
// 256 thr = 8 warps (4m x 2n), warp m32 x n64.
// ========================================================================
#define G_AH 0
#define G_AL 16384
#define G_BH 32768
#define G_BL 49152

__global__ void __launch_bounds__(256)
k_gemm1(const float* __restrict__ h, const float* __restrict__ a) {
    extern __shared__ __align__(1024) char sm[];
    const uint32_t smb = smem_u32(sm);
    __shared__ float as1[128], as2[128];
    const int i0g = blockIdx.x * 128, fy = blockIdx.y;
    const int b = i0g >> 11, jb = i0g & (NN - 1);
    const int t = threadIdx.x, wid = t >> 5, lane = t & 31;
    const int wm = wid & 3, wn = wid >> 2;

    if (t < 128) as1[t] = a[fy * 128 + t];
    else         as2[t - 128] = a[256 + fy * 128 + (t - 128)];

    const uint32_t a_l = (uint32_t)(((wm * 32 + (lane & 15)) << 7) | ((lane >> 4) << 4));
    const uint32_t b_l = (uint32_t)(((wn * 64 + ((lane >> 4) << 3) + (lane & 7)) << 7)
                                    | (((lane >> 3) & 1) << 4));

    float acc[2][8][4];
#pragma unroll
    for (int mt = 0; mt < 2; ++mt)
#pragma unroll
        for (int nt = 0; nt < 8; ++nt)
#pragma unroll
            for (int e = 0; e < 4; ++e) acc[mt][nt][e] = 0.f;

    const int arow = t >> 1, akh = t & 1;
    const float* hp = h + ((size_t)(i0g + arow)) * FF + akh * 32;

    for (int c = 0; c < 4; ++c) {
        const int k0 = c * 64;
        // B: WtH/WtL [128 f][64 k] via cp.async
#pragma unroll
        for (int q = 0; q < 4; ++q) {
            int idx = t + q * 256;
            int f = idx >> 3, seg = idx & 7;
            const unsigned short* sH = g_WtH + (size_t)(fy * 128 + f) * FF + k0 + seg * 8;
            const unsigned short* sL = g_WtL + (size_t)(fy * 128 + f) * FF + k0 + seg * 8;
            uint32_t soff = SWZ128((uint32_t)(f * 128 + seg * 16));
            CPA16(smb + G_BH + soff, sH);
            CPA16(smb + G_BL + soff, sL);
        }
        CPCOMMIT();
        // A: h fp32 -> f16 hi/lo
#pragma unroll
        for (int q = 0; q < 8; ++q) {
            float4 v = *(const float4*)(hp + k0 + q * 4);
            float r0, r1, r2, r3;
            uint32_t h01 = packh2r(v.x, v.y, r0, r1);
            uint32_t h23 = packh2r(v.z, v.w, r2, r3);
            uint32_t l01 = packh2(r0, r1);
            uint32_t l23 = packh2(r2, r3);
            uint32_t base = (uint32_t)(arow * 128 + (akh * 32 + q * 4) * 2);
            uint32_t so = SWZ128(base);
            *(uint2*)(sm + G_AH + so) = make_uint2(h01, h23);
            *(uint2*)(sm + G_AL + so) = make_uint2(l01, l23);
        }
        CPWAIT0();
        __syncthreads();

#pragma unroll
        for (int k16 = 0; k16 < 4; ++k16) {
            uint32_t ahh[2][4], ahl[2][4];
#pragma unroll
            for (int mt = 0; mt < 2; ++mt) {
                uint32_t ao = SWZ128(a_l + (uint32_t)(mt * 2048 + k16 * 32));
                ldsm4(ahh[mt], smb + G_AH + ao);
                ldsm4(ahl[mt], smb + G_AL + ao);
            }
#pragma unroll
            for (int nt2 = 0; nt2 < 4; ++nt2) {
                uint32_t bo = SWZ128(b_l + (uint32_t)(nt2 * 2048 + k16 * 32));
                uint32_t bh[4], bl[4];
                ldsm4(bh, smb + G_BH + bo);
                ldsm4(bl, smb + G_BL + bo);
#pragma unroll
                for (int mt = 0; mt < 2; ++mt) {
                    mmaf16(acc[mt][nt2 * 2 + 0], ahh[mt], bh);
                    mmaf16(acc[mt][nt2 * 2 + 1], ahh[mt], bh + 2);
                    mmaf16(acc[mt][nt2 * 2 + 0], ahl[mt], bh);
                    mmaf16(acc[mt][nt2 * 2 + 1], ahl[mt], bh + 2);
                    mmaf16(acc[mt][nt2 * 2 + 0], ahh[mt], bl);
                    mmaf16(acc[mt][nt2 * 2 + 1], ahh[mt], bl + 2);
                }
            }
        }
        __syncthreads();
    }

    // ---- epilogue: transpose via smem (fp32 [f][i], stride 130) ----
    float* ts = (float*)sm;
    const int tq = lane >> 2, tr = lane & 3;
#pragma unroll
    for (int mt = 0; mt < 2; ++mt) {
        int i_l = wm * 32 + mt * 16 + tq;
#pragma unroll
        for (int nt = 0; nt < 8; ++nt) {
            int f_l = wn * 64 + nt * 8 + tr * 2;
            ts[f_l * 130 + i_l]           = acc[mt][nt][0];
            ts[(f_l + 1) * 130 + i_l]     = acc[mt][nt][1];
            ts[f_l * 130 + i_l + 8]       = acc[mt][nt][2];
            ts[(f_l + 1) * 130 + i_l + 8] = acc[mt][nt][3];
        }
    }
    __syncthreads();

    // s1/s2 partials: thread -> (i, f-half), reduce pair, atomicAdd
    {
        const int i_l = t >> 1, fh = t & 1;
        float s1p = 0.f, s2p = 0.f;
#pragma unroll 8
        for (int f = 0; f < 64; ++f) {
            int fl = fh * 64 + f;
            float v = ts[fl * 130 + i_l];
            s1p += v * as1[fl];
            s2p += v * as2[fl];
        }
        s1p += __shfl_xor_sync(0xffffffffu, s1p, 1);
        s2p += __shfl_xor_sync(0xffffffffu, s2p, 1);
        if (fh == 0) {
            atomicAdd(&g_s1[b * NN + jb + i_l], s1p);
            atomicAdd(&g_s2[b * NN + jb + i_l], s2p);
        }
    }

    // pack f16 hi, store WhT[f][j]
    {
        const int fl = t >> 1, half = t & 1;
        unsigned short* dst = g_WhTh + ((size_t)(b * FF) + fy * 128 + fl) * NN
                              + jb + half * 64;
        const float* src = ts + fl * 130 + half * 64;
#pragma unroll
        for (int q = 0; q < 8; ++q) {
            float v0 = src[q * 8 + 0], v1 = src[q * 8 + 1];
            float v2 = src[q * 8 + 2], v3 = src[q * 8 + 3];
            float v4 = src[q * 8 + 4], v5 = src[q * 8 + 5];
            float v6 = src[q * 8 + 6], v7 = src[q * 8 + 7];
            uint4 hv = make_uint4(packh2(v0, v1), packh2(v2, v3),
                                  packh2(v4, v5), packh2(v6, v7));
            *(uint4*)(dst + q * 8) = hv;
        }
    }
}

// ========================================================================
// Kernel 3: per-row softmax stats
// ========================================================================
__global__ void __launch_bounds__(256)
k_stats() {
    const int i = blockIdx.x, b = blockIdx.y, t = threadIdx.x;
    __shared__ float red[8];
    __shared__ float bval;
    const float s1v = g_s1[b * NN + i];
    const float* s2r = g_s2 + b * NN;
    const ull* mrow = g_mask + i * 32;
    float e[8], mk[8];
    float mx = -3e38f;
#pragma unroll
    for (int q = 0; q < 8; ++q) {
        int j = t + q * 256;
        float x = s1v + s2r[j];
        x = fmaxf(x, 0.2f * x);
        ull wd = mrow[j >> 6];
        float f = (float)((wd >> (j & 63)) & 1ull);
        e[q] = x; mk[q] = f;
        mx = fmaxf(mx, f > 0.f ? x : -3e38f);
    }
#pragma unroll
    for (int off = 16; off > 0; off >>= 1)
        mx = fmaxf(mx, __shfl_xor_sync(0xffffffffu, mx, off));
    if ((t & 31) == 0) red[t >> 5] = mx;
    __syncthreads();
    if (t == 0) {
        float v = red[0];
        for (int w2 = 1; w2 < 8; ++w2) v = fmaxf(v, red[w2]);
        bval = v;
    }
    __syncthreads();
    const float M = bval;
    float s = 0.f;
#pragma unroll
    for (int q = 0; q < 8; ++q)
        s += mk[q] * fexp(fminf(fmaxf(e[q] - M, -80.f), 8.f));
#pragma unroll
    for (int off = 16; off > 0; off >>= 1)
        s += __shfl_xor_sync(0xffffffffu, s, off);
    if ((t & 31) == 0) red[t >> 5] = s;
    __syncthreads();
    if (t == 0) {
        float v = 0.f;
        for (int w2 = 0; w2 < 8; ++w2) v += red[w2];
        g_m[b * NN + i] = M;
        g_iz[b * NN + i] = 1.0f / v;
    }
}

// ========================================================================
// Kernel 4 (mma.sync f16): out = elu(P @ Wh), 1-term (Ph x Whh).
// Grid (16 m, 2 f, 8 b); 256 thr = 8 warps (4m x 2n); warp m32 x n64.
// K=2048 in 32 chunks of 64; cp.async double-buffered (2 x 32 KB).
// ========================================================================
#define BUFSZ 32768
#define O_PH 0
#define O_BH 16384

__global__ void __launch_bounds__(256, 2)
k_attn(float* __restrict__ out) {
    extern __shared__ __align__(1024) char sm[];
    const uint32_t smb = smem_u32(sm);
    const int bz = blockIdx.z, i0 = blockIdx.x * 128, fy = blockIdx.y;
    const int t = threadIdx.x, wid = t >> 5, lane = t & 31;
    const int wm = wid & 3, wn = wid >> 2;

    const int prow = t >> 1, jq = t & 1;
    const float s1r = g_s1[bz * NN + i0 + prow];
    const float mr  = g_m [bz * NN + i0 + prow];
    const float zr  = g_iz[bz * NN + i0 + prow];
    const ull* mrow = g_mask + (size_t)(i0 + prow) * 32;

    const unsigned short* whH = g_WhTh + ((size_t)bz * FF + fy * 128) * NN;
    const float* s2B = g_s2 + bz * NN;

    const uint32_t a_l = (uint32_t)(((wm * 32 + (lane & 15)) << 7) | ((lane >> 4) << 4));
    const uint32_t b_l = (uint32_t)(((wn * 64 + ((lane >> 4) << 3) + (lane & 7)) << 7)
                                    | (((lane >> 3) & 1) << 4));

    float acc[2][8][4];
#pragma unroll
    for (int mt = 0; mt < 2; ++mt)
#pragma unroll
        for (int nt = 0; nt < 8; ++nt)
#pragma unroll
            for (int e = 0; e < 4; ++e) acc[mt][nt][e] = 0.f;

    auto stageB = [&](int c, uint32_t bufa) {
        const int j0 = c * 64;
#pragma unroll
        for (int q = 0; q < 4; ++q) {
            int idx = t + q * 256;
            int f = idx >> 3, seg = idx & 7;
            size_t goff = (size_t)f * NN + j0 + seg * 8;
            uint32_t soff = SWZ128((uint32_t)(f * 128 + seg * 16));
            CPA16(bufa + O_BH + soff, whH + goff);
        }
    };
    auto stageP = [&](int c, char* buf) {
        const int j0 = c * 64;
        ull wd = mrow[j0 >> 6];
        const float* s2p = s2B + j0 + jq * 32;
        uint32_t base = (uint32_t)(prow * 128 + jq * 64);
#pragma unroll
        for (int g = 0; g < 8; ++g) {
            float4 s2v = *(const float4*)(s2p + g * 4);
            float sv[4] = {s2v.x, s2v.y, s2v.z, s2v.w};
            float p[4];
#pragma unroll
            for (int e = 0; e < 4; ++e) {
                int jl = jq * 32 + g * 4 + e;
                float x = s1r + sv[e];
                x = fmaxf(x, 0.2f * x);
                float mkf = (float)((wd >> jl) & 1ull);
                p[e] = mkf * zr * fexp(fminf(fmaxf(x - mr, -80.f), 8.f));
            }
            uint32_t h01 = packh2(p[0], p[1]);
            uint32_t h23 = packh2(p[2], p[3]);
            *(uint2*)(buf + O_PH + SWZ128(base + g * 8)) = make_uint2(h01, h23);
        }
    };

    stageB(0, smb);
    CPCOMMIT();
    stageP(0, sm);

    for (int c = 0; c < 32; ++c) {
        const int p = c & 1;
        const uint32_t bufa = smb + p * BUFSZ;
        char* bufn = sm + (p ^ 1) * BUFSZ;

        if (c < 31) {
            stageB(c + 1, smb + (p ^ 1) * BUFSZ);
            CPCOMMIT();
            stageP(c + 1, bufn);
            CPWAIT1();
        } else {
            CPWAIT0();
        }
        __syncthreads();

#pragma unroll
        for (int k16 = 0; k16 < 4; ++k16) {
            uint32_t ah[2][4];
#pragma unroll
            for (int mt = 0; mt < 2; ++mt)
                ldsm4(ah[mt], bufa + O_PH +
                      SWZ128(a_l + (uint32_t)(mt * 2048 + k16 * 32)));
#pragma unroll
            for (int nt2 = 0; nt2 < 4; ++nt2) {
                uint32_t bo = SWZ128(b_l + (uint32_t)(nt2 * 2048 + k16 * 32));
                uint32_t bh[4];
                ldsm4(bh, bufa + O_BH + bo);
#pragma unroll
                for (int mt = 0; mt < 2; ++mt) {
                    mmaf16(acc[mt][nt2 * 2 + 0], ah[mt], bh);
                    mmaf16(acc[mt][nt2 * 2 + 1], ah[mt], bh + 2);
                }
            }
        }
        __syncthreads();
    }

    const int tq = lane >> 2, tr = lane & 3;
#pragma unroll
    for (int mt = 0; mt < 2; ++mt) {
        int i = i0 + wm * 32 + mt * 16 + tq;
        float* op0 = out + ((size_t)bz * NN + i) * FF + fy * 128 + wn * 64 + tr * 2;
#pragma unroll
        for (int nt = 0; nt < 8; ++nt) {
            float2 v0 = make_float2(elu1(acc[mt][nt][0]), elu1(acc[mt][nt][1]));
            float2 v1 = make_float2(elu1(acc[mt][nt][2]), elu1(acc[mt][nt][3]));
            *(float2*)(op0 + nt * 8) = v0;
            *(float2*)(op0 + nt * 8 + 8 * FF) = v1;
        }
    }
}

// ========================================================================
extern "C" void kernel_launch(void* const* d_in, const int* in_sizes, int n_in,
                              void* d_out, int out_size) {
    const float* h   = (const float*)d_in[0];
    const int*   adj = (const int*)d_in[1];
    const float* W   = (const float*)d_in[2];
    const float* a   = (const float*)d_in[3];
    float* out = (float*)d_out;

    cudaFuncSetAttribute(k_gemm1, cudaFuncAttributeMaxDynamicSharedMemorySize, 66560);
    cudaFuncSetAttribute(k_attn, cudaFuncAttributeMaxDynamicSharedMemorySize, 2 * BUFSZ);

    k_packW<<<FF, FF>>>(W);
    k_mask <<<NN * 32 / 256, 256>>>(adj);
    k_gemm1<<<dim3(128, 2), 256, 66560>>>(h, a);
    k_stats<<<dim3(NN, BB), 256>>>();
    k_attn <<<dim3(16, 2, 8), 256, 2 * BUFSZ>>>(out);
}

// round 7
// speedup vs baseline: 3.6074x; 1.3055x over previous
#include <cuda_runtime.h>
#include <cuda_fp16.h>
#include <cstdint>

#define BB 8
#define NN 2048
#define FF 256

// ---- scratch ----
__device__ unsigned short g_WhTh[BB * FF * NN];   // f16 hi, [b][f][j], 8 MB
__device__ unsigned short g_WtH[FF * FF];         // f16 W^T hi [fout][fin]
__device__ unsigned short g_WtL[FF * FF];         // f16 W^T lo
__device__ float g_s1[BB * NN];
__device__ float g_s2[BB * NN];
__device__ float g_smax[BB];
__device__ unsigned long long g_mask[NN * 32];

typedef unsigned long long ull;

// FFMA-only expf. Valid for x in [-80, 10], rel err ~3e-6.
__device__ __forceinline__ float fexp(float x) {
    const float L2E = 1.4426950408889634f;
    float t = fmaf(x, L2E, 12582912.0f);
    int   k = __float_as_int(t);
    float r = t - 12582912.0f;
    float f = fmaf(x, L2E, -r);
    float p = 1.33335581e-3f;
    p = fmaf(p, f, 9.61812910e-3f);
    p = fmaf(p, f, 5.55041086e-2f);
    p = fmaf(p, f, 2.40226507e-1f);
    p = fmaf(p, f, 6.93147182e-1f);
    p = fmaf(p, f, 1.0f);
    return __int_as_float(__float_as_int(p) + (k << 23));
}
__device__ __forceinline__ float elu1(float x) {
    return x > 0.f ? x : fexp(fmaxf(x, -80.f)) - 1.f;
}
__device__ __forceinline__ uint32_t packh2r(float a, float b, float& ra, float& rb) {
    __half ha = __float2half_rn(a), hb = __float2half_rn(b);
    ra = a - __half2float(ha);
    rb = b - __half2float(hb);
    __half2 h2 = __halves2half2(ha, hb);
    return reinterpret_cast<uint32_t&>(h2);
}
__device__ __forceinline__ uint32_t packh2(float a, float b) {
    __half2 h2 = __floats2half2_rn(a, b);
    return reinterpret_cast<uint32_t&>(h2);
}

#define SWZ128(o) ((o) ^ (((o) >> 3) & 0x70))

// ---- mma.sync / ldmatrix / cp.async ----
__device__ __forceinline__ void ldsm4(uint32_t* r, uint32_t a) {
    asm volatile("ldmatrix.sync.aligned.m8n8.x4.shared.b16 {%0,%1,%2,%3}, [%4];"
        : "=r"(r[0]), "=r"(r[1]), "=r"(r[2]), "=r"(r[3]) : "r"(a));
}
__device__ __forceinline__ void mmaf16(float* c, const uint32_t* a, const uint32_t* b) {
    asm volatile(
        "mma.sync.aligned.m16n8k16.row.col.f32.f16.f16.f32 "
        "{%0,%1,%2,%3}, {%4,%5,%6,%7}, {%8,%9}, {%0,%1,%2,%3};"
        : "+f"(c[0]), "+f"(c[1]), "+f"(c[2]), "+f"(c[3])
        : "r"(a[0]), "r"(a[1]), "r"(a[2]), "r"(a[3]), "r"(b[0]), "r"(b[1]));
}
__device__ __forceinline__ uint32_t smem_u32(const void* p) {
    uint32_t a;
    asm("{ .reg .u64 t; cvta.to.shared.u64 t, %1; cvt.u32.u64 %0, t; }"
        : "=r"(a) : "l"(p));
    return a;
}
#define CPA16(dst, src) asm volatile( \
    "cp.async.cg.shared.global [%0], [%1], 16;" :: "r"(dst), "l"(src))
#define CPCOMMIT() asm volatile("cp.async.commit_group;" ::: "memory")
#define CPWAIT1() asm volatile("cp.async.wait_group 1;" ::: "memory")
#define CPWAIT0() asm volatile("cp.async.wait_group 0;" ::: "memory")

// ========================================================================
// Kernel 0: pack W -> f16 hi/lo, transposed [fout][fin]
// ========================================================================
__global__ void k_packW(const float* __restrict__ W) {
    const int fo = blockIdx.x, fi = threadIdx.x;
    float v = W[fi * FF + fo];
    float r0, dummy;
    uint32_t hp = packh2r(v, 0.f, r0, dummy);
    g_WtH[fo * FF + fi] = (unsigned short)(hp & 0xffff);
    g_WtL[fo * FF + fi] = (unsigned short)(packh2(r0, 0.f) & 0xffff);
}

// ========================================================================
// Kernel 1: pack mask bits (thread -> 16 bits, coalesced int4 loads)
//           + zero s1/s2 for gemm1 atomics.
// ========================================================================
__global__ void __launch_bounds__(256)
k_mask(const int* __restrict__ adj) {
    const int gid = blockIdx.x * 256 + threadIdx.x;      // 0..262143
    if (gid < BB * NN) { g_s1[gid] = 0.f; g_s2[gid] = 0.f; }
    const int i = gid >> 7, seg = gid & 127;             // 16 j's per thread
    const int4* src = (const int4*)(adj + (size_t)i * NN + seg * 16);
    unsigned int m = 0;
#pragma unroll
    for (int q = 0; q < 4; ++q) {
        int4 v = src[q];
        if (v.x > 0) m |= 1u << (q * 4 + 0);
        if (v.y > 0) m |= 1u << (q * 4 + 1);
        if (v.z > 0) m |= 1u << (q * 4 + 2);
        if (v.w > 0) m |= 1u << (q * 4 + 3);
    }
    int d = i - seg * 16;
    if (d >= 0 && d < 16) m |= 1u << d;
    ((unsigned short*)g_mask)[gid] = (unsigned short)m;
}

// ========================================================================
// Kernel 2 (mma): Wh = h @ W (3-term f16 split, fp32-accurate).
// Emits WhT-hi f16 [b][f][j] + s1/s2 (fp32, atomicAdd partials).
// ========================================================================
#define G_AH 0
#define G_AL 16384
#define G_BH 32768
#define G_BL 49152

__global__ void __launch_bounds__(256)
k_gemm1(const float* __restrict__ h, const float* __restrict__ a) {
    extern __shared__ __align__(1024) char sm[];
    const uint32_t smb = smem_u32(sm);
    __shared__ float as1[128], as2[128];
    const int i0g = blockIdx.x * 128, fy = blockIdx.y;
    const int b = i0g >> 11, jb = i0g & (NN - 1);
    const int t = threadIdx.x, wid = t >> 5, lane = t & 31;
    const int wm = wid & 3, wn = wid >> 2;

    if (t < 128) as1[t] = a[fy * 128 + t];
    else         as2[t - 128] = a[256 + fy * 128 + (t - 128)];

    const uint32_t a_l = (uint32_t)(((wm * 32 + (lane & 15)) << 7) | ((lane >> 4) << 4));
    const uint32_t b_l = (uint32_t)(((wn * 64 + ((lane >> 4) << 3) + (lane & 7)) << 7)
                                    | (((lane >> 3) & 1) << 4));

    float acc[2][8][4];
#pragma unroll
    for (int mt = 0; mt < 2; ++mt)
#pragma unroll
        for (int nt = 0; nt < 8; ++nt)
#pragma unroll
            for (int e = 0; e < 4; ++e) acc[mt][nt][e] = 0.f;

    const int arow = t >> 1, akh = t & 1;
    const float* hp = h + ((size_t)(i0g + arow)) * FF + akh * 32;

    for (int c = 0; c < 4; ++c) {
        const int k0 = c * 64;
#pragma unroll
        for (int q = 0; q < 4; ++q) {
            int idx = t + q * 256;
            int f = idx >> 3, seg = idx & 7;
            const unsigned short* sH = g_WtH + (size_t)(fy * 128 + f) * FF + k0 + seg * 8;
            const unsigned short* sL = g_WtL + (size_t)(fy * 128 + f) * FF + k0 + seg * 8;
            uint32_t soff = SWZ128((uint32_t)(f * 128 + seg * 16));
            CPA16(smb + G_BH + soff, sH);
            CPA16(smb + G_BL + soff, sL);
        }
        CPCOMMIT();
#pragma unroll
        for (int q = 0; q < 8; ++q) {
            float4 v = *(const float4*)(hp + k0 + q * 4);
            float r0, r1, r2, r3;
            uint32_t h01 = packh2r(v.x, v.y, r0, r1);
            uint32_t h23 = packh2r(v.z, v.w, r2, r3);
            uint32_t l01 = packh2(r0, r1);
            uint32_t l23 = packh2(r2, r3);
            uint32_t base = (uint32_t)(arow * 128 + (akh * 32 + q * 4) * 2);
            uint32_t so = SWZ128(base);
            *(uint2*)(sm + G_AH + so) = make_uint2(h01, h23);
            *(uint2*)(sm + G_AL + so) = make_uint2(l01, l23);
        }
        CPWAIT0();
        __syncthreads();

#pragma unroll
        for (int k16 = 0; k16 < 4; ++k16) {
            uint32_t ahh[2][4], ahl[2][4];
#pragma unroll
            for (int mt = 0; mt < 2; ++mt) {
                uint32_t ao = SWZ128(a_l + (uint32_t)(mt * 2048 + k16 * 32));
                ldsm4(ahh[mt], smb + G_AH + ao);
                ldsm4(ahl[mt], smb + G_AL + ao);
            }
#pragma unroll
            for (int nt2 = 0; nt2 < 4; ++nt2) {
                uint32_t bo = SWZ128(b_l + (uint32_t)(nt2 * 2048 + k16 * 32));
                uint32_t bh[4], bl[4];
                ldsm4(bh, smb + G_BH + bo);
                ldsm4(bl, smb + G_BL + bo);
#pragma unroll
                for (int mt = 0; mt < 2; ++mt) {
                    mmaf16(acc[mt][nt2 * 2 + 0], ahh[mt], bh);
                    mmaf16(acc[mt][nt2 * 2 + 1], ahh[mt], bh + 2);
                    mmaf16(acc[mt][nt2 * 2 + 0], ahl[mt], bh);
                    mmaf16(acc[mt][nt2 * 2 + 1], ahl[mt], bh + 2);
                    mmaf16(acc[mt][nt2 * 2 + 0], ahh[mt], bl);
                    mmaf16(acc[mt][nt2 * 2 + 1], ahh[mt], bl + 2);
                }
            }
        }
        __syncthreads();
    }

    // ---- epilogue: transpose via smem (fp32 [f][i], stride 130) ----
    float* ts = (float*)sm;
    const int tq = lane >> 2, tr = lane & 3;
#pragma unroll
    for (int mt = 0; mt < 2; ++mt) {
        int i_l = wm * 32 + mt * 16 + tq;
#pragma unroll
        for (int nt = 0; nt < 8; ++nt) {
            int f_l = wn * 64 + nt * 8 + tr * 2;
            ts[f_l * 130 + i_l]           = acc[mt][nt][0];
            ts[(f_l + 1) * 130 + i_l]     = acc[mt][nt][1];
            ts[f_l * 130 + i_l + 8]       = acc[mt][nt][2];
            ts[(f_l + 1) * 130 + i_l + 8] = acc[mt][nt][3];
        }
    }
    __syncthreads();

    {
        const int i_l = t >> 1, fh = t & 1;
        float s1p = 0.f, s2p = 0.f;
#pragma unroll 8
        for (int f = 0; f < 64; ++f) {
            int fl = fh * 64 + f;
            float v = ts[fl * 130 + i_l];
            s1p += v * as1[fl];
            s2p += v * as2[fl];
        }
        s1p += __shfl_xor_sync(0xffffffffu, s1p, 1);
        s2p += __shfl_xor_sync(0xffffffffu, s2p, 1);
        if (fh == 0) {
            atomicAdd(&g_s1[b * NN + jb + i_l], s1p);
            atomicAdd(&g_s2[b * NN + jb + i_l], s2p);
        }
    }

    {
        const int fl = t >> 1, half = t & 1;
        unsigned short* dst = g_WhTh + ((size_t)(b * FF) + fy * 128 + fl) * NN
                              + jb + half * 64;
        const float* src = ts + fl * 130 + half * 64;
#pragma unroll
        for (int q = 0; q < 8; ++q) {
            float v0 = src[q * 8 + 0], v1 = src[q * 8 + 1];
            float v2 = src[q * 8 + 2], v3 = src[q * 8 + 3];
            float v4 = src[q * 8 + 4], v5 = src[q * 8 + 5];
            float v6 = src[q * 8 + 6], v7 = src[q * 8 + 7];
            uint4 hv = make_uint4(packh2(v0, v1), packh2(v2, v3),
                                  packh2(v4, v5), packh2(v6, v7));
            *(uint4*)(dst + q * 8) = hv;
        }
    }
}

// ========================================================================
// Kernel 3: per-batch unmasked max of s2 (softmax shift upper bound)
// ========================================================================
__global__ void __launch_bounds__(256)
k_smax() {
    const int b = blockIdx.x, t = threadIdx.x;
    __shared__ float red[8];
    float mx = -3e38f;
#pragma unroll
    for (int q = 0; q < 8; ++q)
        mx = fmaxf(mx, g_s2[b * NN + t + q * 256]);
#pragma unroll
    for (int off = 16; off > 0; off >>= 1)
        mx = fmaxf(mx, __shfl_xor_sync(0xffffffffu, mx, off));
    if ((t & 31) == 0) red[t >> 5] = mx;
    __syncthreads();
    if (t == 0) {
        float v = red[0];
        for (int w = 1; w < 8; ++w) v = fmaxf(v, red[w]);
        g_smax[b] = v;
    }
}

// ========================================================================
// Kernel 4 (mma.sync f16): out = elu((P_u @ Wh) / Z), fused normalizer.
// M_i = lrelu(s1_i + max_j s2_j) >= all masked scores (monotonicity).
// Z accumulated in registers during P production; epilogue divides.
// ========================================================================
#define BUFSZ 32768
#define O_PH 0
#define O_BH 16384

__global__ void __launch_bounds__(256, 2)
k_attn(float* __restrict__ out) {
    extern __shared__ __align__(1024) char sm[];
    const uint32_t smb = smem_u32(sm);
    const int bz = blockIdx.z, i0 = blockIdx.x * 128, fy = blockIdx.y;
    const int t = threadIdx.x, wid = t >> 5, lane = t & 31;
    const int wm = wid & 3, wn = wid >> 2;

    const int prow = t >> 1, jq = t & 1;
    const float s1r = g_s1[bz * NN + i0 + prow];
    const float smax = g_smax[bz];
    float Mx = s1r + smax;
    const float Mi = fmaxf(Mx, 0.2f * Mx);        // lrelu: row softmax shift
    const ull* mrow = g_mask + (size_t)(i0 + prow) * 32;

    const unsigned short* whH = g_WhTh + ((size_t)bz * FF + fy * 128) * NN;
    const float* s2B = g_s2 + bz * NN;

    const uint32_t a_l = (uint32_t)(((wm * 32 + (lane & 15)) << 7) | ((lane >> 4) << 4));
    const uint32_t b_l = (uint32_t)(((wn * 64 + ((lane >> 4) << 3) + (lane & 7)) << 7)
                                    | (((lane >> 3) & 1) << 4));

    float acc[2][8][4];
#pragma unroll
    for (int mt = 0; mt < 2; ++mt)
#pragma unroll
        for (int nt = 0; nt < 8; ++nt)
#pragma unroll
            for (int e = 0; e < 4; ++e) acc[mt][nt][e] = 0.f;
    float zacc = 0.f;

    auto stageB = [&](int c, uint32_t bufa) {
        const int j0 = c * 64;
#pragma unroll
        for (int q = 0; q < 4; ++q) {
            int idx = t + q * 256;
            int f = idx >> 3, seg = idx & 7;
            size_t goff = (size_t)f * NN + j0 + seg * 8;
            uint32_t soff = SWZ128((uint32_t)(f * 128 + seg * 16));
            CPA16(bufa + O_BH + soff, whH + goff);
        }
    };
    auto stageP = [&](int c, char* buf) {
        const int j0 = c * 64;
        ull wd = mrow[j0 >> 6];
        const float* s2p = s2B + j0 + jq * 32;
        uint32_t base = (uint32_t)(prow * 128 + jq * 64);
#pragma unroll
        for (int g = 0; g < 8; ++g) {
            float4 s2v = *(const float4*)(s2p + g * 4);
            float sv[4] = {s2v.x, s2v.y, s2v.z, s2v.w};
            float p[4];
#pragma unroll
            for (int e = 0; e < 4; ++e) {
                int jl = jq * 32 + g * 4 + e;
                float x = s1r + sv[e];
                x = fmaxf(x, 0.2f * x);
                float mkf = (float)((wd >> jl) & 1ull);
                p[e] = mkf * fexp(fmaxf(x - Mi, -80.f));
                zacc += p[e];
            }
            uint32_t h01 = packh2(p[0], p[1]);
            uint32_t h23 = packh2(p[2], p[3]);
            *(uint2*)(buf + O_PH + SWZ128(base + g * 8)) = make_uint2(h01, h23);
        }
    };

    stageB(0, smb);
    CPCOMMIT();
    stageP(0, sm);

    for (int c = 0; c < 32; ++c) {
        const int p = c & 1;
        const uint32_t bufa = smb + p * BUFSZ;
        char* bufn = sm + (p ^ 1) * BUFSZ;

        if (c < 31) {
            stageB(c + 1, smb + (p ^ 1) * BUFSZ);
            CPCOMMIT();
            stageP(c + 1, bufn);
            CPWAIT1();
        } else {
            CPWAIT0();
        }
        __syncthreads();

#pragma unroll
        for (int k16 = 0; k16 < 4; ++k16) {
            uint32_t ah[2][4];
#pragma unroll
            for (int mt = 0; mt < 2; ++mt)
                ldsm4(ah[mt], bufa + O_PH +
                      SWZ128(a_l + (uint32_t)(mt * 2048 + k16 * 32)));
#pragma unroll
            for (int nt2 = 0; nt2 < 4; ++nt2) {
                uint32_t bo = SWZ128(b_l + (uint32_t)(nt2 * 2048 + k16 * 32));
                uint32_t bh[4];
                ldsm4(bh, bufa + O_BH + bo);
#pragma unroll
                for (int mt = 0; mt < 2; ++mt) {
                    mmaf16(acc[mt][nt2 * 2 + 0], ah[mt], bh);
                    mmaf16(acc[mt][nt2 * 2 + 1], ah[mt], bh + 2);
                }
            }
        }
        __syncthreads();
    }

    // ---- Z reduce: pairs (jq 0/1) share prow ----
    float* zs = (float*)sm;
    zacc += __shfl_xor_sync(0xffffffffu, zacc, 1);
    if (jq == 0) zs[prow] = 1.0f / zacc;    // diag in mask -> zacc > 0
    __syncthreads();

    // ---- epilogue: normalize + ELU + store ----
    const int tq = lane >> 2, tr = lane & 3;
#pragma unroll
    for (int mt = 0; mt < 2; ++mt) {
        int il = wm * 32 + mt * 16 + tq;
        float iz0 = zs[il], iz1 = zs[il + 8];
        int i = i0 + il;
        float* op0 = out + ((size_t)bz * NN + i) * FF + fy * 128 + wn * 64 + tr * 2;
#pragma unroll
        for (int nt = 0; nt < 8; ++nt) {
            float2 v0 = make_float2(elu1(acc[mt][nt][0] * iz0),
                                    elu1(acc[mt][nt][1] * iz0));
            float2 v1 = make_float2(elu1(acc[mt][nt][2] * iz1),
                                    elu1(acc[mt][nt][3] * iz1));
            *(float2*)(op0 + nt * 8) = v0;
            *(float2*)(op0 + nt * 8 + 8 * FF) = v1;
        }
    }
}

// ========================================================================
extern "C" void kernel_launch(void* const* d_in, const int* in_sizes, int n_in,
                              void* d_out, int out_size) {
    const float* h   = (const float*)d_in[0];
    const int*   adj = (const int*)d_in[1];
    const float* W   = (const float*)d_in[2];
    const float* a   = (const float*)d_in[3];
    float* out = (float*)d_out;

    cudaFuncSetAttribute(k_gemm1, cudaFuncAttributeMaxDynamicSharedMemorySize, 66560);
    cudaFuncSetAttribute(k_attn, cudaFuncAttributeMaxDynamicSharedMemorySize, 2 * BUFSZ);

    k_packW<<<FF, FF>>>(W);
    k_mask <<<NN * 128 / 256, 256>>>(adj);
    k_gemm1<<<dim3(128, 2), 256, 66560>>>(h, a);
    k_smax <<<BB, 256>>>();
    k_attn <<<dim3(16, 2, 8), 256, 2 * BUFSZ>>>(out);
}

// round 8
// speedup vs baseline: 5.0865x; 1.4100x over previous
#include <cuda_runtime.h>
#include <cuda_fp16.h>
#include <cstdint>

#define BB 8
#define NN 2048
#define FF 256

// ---- scratch ----
__device__ unsigned short g_WhTh[BB * FF * NN];   // f16 hi, [b][f][j], 8 MB
__device__ unsigned short g_WtH[FF * FF];         // f16 W^T hi [fout][fin]
__device__ unsigned short g_WtL[FF * FF];         // f16 W^T lo
__device__ float g_s1[BB * NN];
__device__ float g_s2[BB * NN];
__device__ float g_smax[BB];
__device__ unsigned long long g_mask[NN * 32];

typedef unsigned long long ull;

// FFMA-only expf. Valid for x in [-80, 10], rel err ~3e-6.
__device__ __forceinline__ float fexp(float x) {
    const float L2E = 1.4426950408889634f;
    float t = fmaf(x, L2E, 12582912.0f);
    int   k = __float_as_int(t);
    float r = t - 12582912.0f;
    float f = fmaf(x, L2E, -r);
    float p = 1.33335581e-3f;
    p = fmaf(p, f, 9.61812910e-3f);
    p = fmaf(p, f, 5.55041086e-2f);
    p = fmaf(p, f, 2.40226507e-1f);
    p = fmaf(p, f, 6.93147182e-1f);
    p = fmaf(p, f, 1.0f);
    return __int_as_float(__float_as_int(p) + (k << 23));
}
__device__ __forceinline__ float elu1(float x) {
    return x > 0.f ? x : fexp(fmaxf(x, -80.f)) - 1.f;
}
__device__ __forceinline__ uint32_t packh2r(float a, float b, float& ra, float& rb) {
    __half ha = __float2half_rn(a), hb = __float2half_rn(b);
    ra = a - __half2float(ha);
    rb = b - __half2float(hb);
    __half2 h2 = __halves2half2(ha, hb);
    return reinterpret_cast<uint32_t&>(h2);
}
__device__ __forceinline__ uint32_t packh2(float a, float b) {
    __half2 h2 = __floats2half2_rn(a, b);
    return reinterpret_cast<uint32_t&>(h2);
}

#define SWZ128(o) ((o) ^ (((o) >> 3) & 0x70))

// ---- mma.sync / ldmatrix / cp.async ----
__device__ __forceinline__ void ldsm4(uint32_t* r, uint32_t a) {
    asm volatile("ldmatrix.sync.aligned.m8n8.x4.shared.b16 {%0,%1,%2,%3}, [%4];"
        : "=r"(r[0]), "=r"(r[1]), "=r"(r[2]), "=r"(r[3]) : "r"(a));
}
__device__ __forceinline__ void mmaf16(float* c, const uint32_t* a, const uint32_t* b) {
    asm volatile(
        "mma.sync.aligned.m16n8k16.row.col.f32.f16.f16.f32 "
        "{%0,%1,%2,%3}, {%4,%5,%6,%7}, {%8,%9}, {%0,%1,%2,%3};"
        : "+f"(c[0]), "+f"(c[1]), "+f"(c[2]), "+f"(c[3])
        : "r"(a[0]), "r"(a[1]), "r"(a[2]), "r"(a[3]), "r"(b[0]), "r"(b[1]));
}
__device__ __forceinline__ uint32_t smem_u32(const void* p) {
    uint32_t a;
    asm("{ .reg .u64 t; cvta.to.shared.u64 t, %1; cvt.u32.u64 %0, t; }"
        : "=r"(a) : "l"(p));
    return a;
}
#define CPA16(dst, src) asm volatile( \
    "cp.async.cg.shared.global [%0], [%1], 16;" :: "r"(dst), "l"(src))
#define CPCOMMIT() asm volatile("cp.async.commit_group;" ::: "memory")
#define CPWAIT1() asm volatile("cp.async.wait_group 1;" ::: "memory")
#define CPWAIT0() asm volatile("cp.async.wait_group 0;" ::: "memory")

// ========================================================================
// Kernel 0: pack W -> f16 hi/lo, transposed [fout][fin]
// ========================================================================
__global__ void k_packW(const float* __restrict__ W) {
    const int fo = blockIdx.x, fi = threadIdx.x;
    float v = W[fi * FF + fo];
    float r0, dummy;
    uint32_t hp = packh2r(v, 0.f, r0, dummy);
    g_WtH[fo * FF + fi] = (unsigned short)(hp & 0xffff);
    g_WtL[fo * FF + fi] = (unsigned short)(packh2(r0, 0.f) & 0xffff);
}

// ========================================================================
// Kernel 1: pack mask bits + zero s1/s2
// ========================================================================
__global__ void __launch_bounds__(256)
k_mask(const int* __restrict__ adj) {
    const int gid = blockIdx.x * 256 + threadIdx.x;
    if (gid < BB * NN) { g_s1[gid] = 0.f; g_s2[gid] = 0.f; }
    const int i = gid >> 7, seg = gid & 127;
    const int4* src = (const int4*)(adj + (size_t)i * NN + seg * 16);
    unsigned int m = 0;
#pragma unroll
    for (int q = 0; q < 4; ++q) {
        int4 v = src[q];
        if (v.x > 0) m |= 1u << (q * 4 + 0);
        if (v.y > 0) m |= 1u << (q * 4 + 1);
        if (v.z > 0) m |= 1u << (q * 4 + 2);
        if (v.w > 0) m |= 1u << (q * 4 + 3);
    }
    int d = i - seg * 16;
    if (d >= 0 && d < 16) m |= 1u << d;
    ((unsigned short*)g_mask)[gid] = (unsigned short)m;
}

// ========================================================================
// Kernel 2 (mma): Wh = h @ W (3-term f16 split, fp32-accurate).
// ========================================================================
#define G_AH 0
#define G_AL 16384
#define G_BH 32768
#define G_BL 49152

__global__ void __launch_bounds__(256)
k_gemm1(const float* __restrict__ h, const float* __restrict__ a) {
    extern __shared__ __align__(1024) char sm[];
    const uint32_t smb = smem_u32(sm);
    __shared__ float as1[128], as2[128];
    const int i0g = blockIdx.x * 128, fy = blockIdx.y;
    const int b = i0g >> 11, jb = i0g & (NN - 1);
    const int t = threadIdx.x, wid = t >> 5, lane = t & 31;
    const int wm = wid & 3, wn = wid >> 2;

    if (t < 128) as1[t] = a[fy * 128 + t];
    else         as2[t - 128] = a[256 + fy * 128 + (t - 128)];

    const uint32_t a_l = (uint32_t)(((wm * 32 + (lane & 15)) << 7) | ((lane >> 4) << 4));
    const uint32_t b_l = (uint32_t)(((wn * 64 + ((lane >> 4) << 3) + (lane & 7)) << 7)
                                    | (((lane >> 3) & 1) << 4));

    float acc[2][8][4];
#pragma unroll
    for (int mt = 0; mt < 2; ++mt)
#pragma unroll
        for (int nt = 0; nt < 8; ++nt)
#pragma unroll
            for (int e = 0; e < 4; ++e) acc[mt][nt][e] = 0.f;

    const int arow = t >> 1, akh = t & 1;
    const float* hp = h + ((size_t)(i0g + arow)) * FF + akh * 32;

    for (int c = 0; c < 4; ++c) {
        const int k0 = c * 64;
#pragma unroll
        for (int q = 0; q < 4; ++q) {
            int idx = t + q * 256;
            int f = idx >> 3, seg = idx & 7;
            const unsigned short* sH = g_WtH + (size_t)(fy * 128 + f) * FF + k0 + seg * 8;
            const unsigned short* sL = g_WtL + (size_t)(fy * 128 + f) * FF + k0 + seg * 8;
            uint32_t soff = SWZ128((uint32_t)(f * 128 + seg * 16));
            CPA16(smb + G_BH + soff, sH);
            CPA16(smb + G_BL + soff, sL);
        }
        CPCOMMIT();
#pragma unroll
        for (int q = 0; q < 8; ++q) {
            float4 v = *(const float4*)(hp + k0 + q * 4);
            float r0, r1, r2, r3;
            uint32_t h01 = packh2r(v.x, v.y, r0, r1);
            uint32_t h23 = packh2r(v.z, v.w, r2, r3);
            uint32_t l01 = packh2(r0, r1);
            uint32_t l23 = packh2(r2, r3);
            uint32_t base = (uint32_t)(arow * 128 + (akh * 32 + q * 4) * 2);
            uint32_t so = SWZ128(base);
            *(uint2*)(sm + G_AH + so) = make_uint2(h01, h23);
            *(uint2*)(sm + G_AL + so) = make_uint2(l01, l23);
        }
        CPWAIT0();
        __syncthreads();

#pragma unroll
        for (int k16 = 0; k16 < 4; ++k16) {
            uint32_t ahh[2][4], ahl[2][4];
#pragma unroll
            for (int mt = 0; mt < 2; ++mt) {
                uint32_t ao = SWZ128(a_l + (uint32_t)(mt * 2048 + k16 * 32));
                ldsm4(ahh[mt], smb + G_AH + ao);
                ldsm4(ahl[mt], smb + G_AL + ao);
            }
#pragma unroll
            for (int nt2 = 0; nt2 < 4; ++nt2) {
                uint32_t bo = SWZ128(b_l + (uint32_t)(nt2 * 2048 + k16 * 32));
                uint32_t bh[4], bl[4];
                ldsm4(bh, smb + G_BH + bo);
                ldsm4(bl, smb + G_BL + bo);
#pragma unroll
                for (int mt = 0; mt < 2; ++mt) {
                    mmaf16(acc[mt][nt2 * 2 + 0], ahh[mt], bh);
                    mmaf16(acc[mt][nt2 * 2 + 1], ahh[mt], bh + 2);
                    mmaf16(acc[mt][nt2 * 2 + 0], ahl[mt], bh);
                    mmaf16(acc[mt][nt2 * 2 + 1], ahl[mt], bh + 2);
                    mmaf16(acc[mt][nt2 * 2 + 0], ahh[mt], bl);
                    mmaf16(acc[mt][nt2 * 2 + 1], ahh[mt], bl + 2);
                }
            }
        }
        __syncthreads();
    }

    // ---- epilogue: transpose via smem (fp32 [f][i], stride 130) ----
    float* ts = (float*)sm;
    const int tq = lane >> 2, tr = lane & 3;
#pragma unroll
    for (int mt = 0; mt < 2; ++mt) {
        int i_l = wm * 32 + mt * 16 + tq;
#pragma unroll
        for (int nt = 0; nt < 8; ++nt) {
            int f_l = wn * 64 + nt * 8 + tr * 2;
            ts[f_l * 130 + i_l]           = acc[mt][nt][0];
            ts[(f_l + 1) * 130 + i_l]     = acc[mt][nt][1];
            ts[f_l * 130 + i_l + 8]       = acc[mt][nt][2];
            ts[(f_l + 1) * 130 + i_l + 8] = acc[mt][nt][3];
        }
    }
    __syncthreads();

    {
        const int i_l = t >> 1, fh = t & 1;
        float s1p = 0.f, s2p = 0.f;
#pragma unroll 8
        for (int f = 0; f < 64; ++f) {
            int fl = fh * 64 + f;
            float v = ts[fl * 130 + i_l];
            s1p += v * as1[fl];
            s2p += v * as2[fl];
        }
        s1p += __shfl_xor_sync(0xffffffffu, s1p, 1);
        s2p += __shfl_xor_sync(0xffffffffu, s2p, 1);
        if (fh == 0) {
            atomicAdd(&g_s1[b * NN + jb + i_l], s1p);
            atomicAdd(&g_s2[b * NN + jb + i_l], s2p);
        }
    }

    {
        const int fl = t >> 1, half = t & 1;
        unsigned short* dst = g_WhTh + ((size_t)(b * FF) + fy * 128 + fl) * NN
                              + jb + half * 64;
        const float* src = ts + fl * 130 + half * 64;
#pragma unroll
        for (int q = 0; q < 8; ++q) {
            float v0 = src[q * 8 + 0], v1 = src[q * 8 + 1];
            float v2 = src[q * 8 + 2], v3 = src[q * 8 + 3];
            float v4 = src[q * 8 + 4], v5 = src[q * 8 + 5];
            float v6 = src[q * 8 + 6], v7 = src[q * 8 + 7];
            uint4 hv = make_uint4(packh2(v0, v1), packh2(v2, v3),
                                  packh2(v4, v5), packh2(v6, v7));
            *(uint4*)(dst + q * 8) = hv;
        }
    }
}

// ========================================================================
// Kernel 3: per-batch unmasked max of s2
// ========================================================================
__global__ void __launch_bounds__(256)
k_smax() {
    const int b = blockIdx.x, t = threadIdx.x;
    __shared__ float red[8];
    float mx = -3e38f;
#pragma unroll
    for (int q = 0; q < 8; ++q)
        mx = fmaxf(mx, g_s2[b * NN + t + q * 256]);
#pragma unroll
    for (int off = 16; off > 0; off >>= 1)
        mx = fmaxf(mx, __shfl_xor_sync(0xffffffffu, mx, off));
    if ((t & 31) == 0) red[t >> 5] = mx;
    __syncthreads();
    if (t == 0) {
        float v = red[0];
        for (int w = 1; w < 8; ++w) v = fmaxf(v, red[w]);
        g_smax[b] = v;
    }
}

// ========================================================================
// Kernel 4 (mma.sync f16): out = elu((P_u @ Wh) / Z), fused normalizer.
// CTA tile M=64 x N=256 (full f — P computed ONCE per (i, j)).
// 256 thr = 8 warps (2m x 4n); warp m32 x n64; j-chunks of 64.
// Per-buffer: P[64][64] 8 KB + B[256][64] 32 KB = 40 KB; double-buffered.
// ========================================================================
#define BUFSZ 40960
#define O_PH 0
#define O_BH 8192

__global__ void __launch_bounds__(256, 2)
k_attn(float* __restrict__ out) {
    extern __shared__ __align__(1024) char sm[];
    const uint32_t smb = smem_u32(sm);
    const int bz = blockIdx.y, i0 = blockIdx.x * 64;
    const int t = threadIdx.x, wid = t >> 5, lane = t & 31;
    const int wm = wid & 1, wn = wid >> 1;

    const int prow = t >> 2, jq = t & 3;          // 64 rows x 16 j per thread
    const float s1r = g_s1[bz * NN + i0 + prow];
    const float smax = g_smax[bz];
    float Mx = s1r + smax;
    const float Mi = fmaxf(Mx, 0.2f * Mx);
    const ull* mrow = g_mask + (size_t)(i0 + prow) * 32;

    const unsigned short* whH = g_WhTh + (size_t)bz * FF * NN;
    const float* s2B = g_s2 + bz * NN;

    const uint32_t a_l = (uint32_t)(((wm * 32 + (lane & 15)) << 7) | ((lane >> 4) << 4));
    const uint32_t b_l = (uint32_t)(((wn * 64 + ((lane >> 4) << 3) + (lane & 7)) << 7)
                                    | (((lane >> 3) & 1) << 4));

    float acc[2][8][4];
#pragma unroll
    for (int mt = 0; mt < 2; ++mt)
#pragma unroll
        for (int nt = 0; nt < 8; ++nt)
#pragma unroll
            for (int e = 0; e < 4; ++e) acc[mt][nt][e] = 0.f;
    float zacc = 0.f;

    auto stageB = [&](int c, uint32_t bufa) {
        const int j0 = c * 64;
#pragma unroll
        for (int q = 0; q < 8; ++q) {
            int idx = t + q * 256;                 // 0..2047
            int f = idx >> 3, seg = idx & 7;
            size_t goff = (size_t)f * NN + j0 + seg * 8;
            uint32_t soff = SWZ128((uint32_t)(f * 128 + seg * 16));
            CPA16(bufa + O_BH + soff, whH + goff);
        }
    };
    auto stageP = [&](int c, char* buf) {
        const int j0 = c * 64;
        ull wd = mrow[j0 >> 6];
        const float* s2p = s2B + j0 + jq * 16;
        uint32_t base = (uint32_t)(prow * 128 + jq * 32);
#pragma unroll
        for (int g = 0; g < 4; ++g) {
            float4 s2v = *(const float4*)(s2p + g * 4);
            float sv[4] = {s2v.x, s2v.y, s2v.z, s2v.w};
            float p[4];
#pragma unroll
            for (int e = 0; e < 4; ++e) {
                int jl = jq * 16 + g * 4 + e;
                float x = s1r + sv[e];
                x = fmaxf(x, 0.2f * x);
                float mkf = (float)((wd >> jl) & 1ull);
                p[e] = mkf * fexp(fmaxf(x - Mi, -80.f));
                zacc += p[e];
            }
            uint32_t h01 = packh2(p[0], p[1]);
            uint32_t h23 = packh2(p[2], p[3]);
            *(uint2*)(buf + O_PH + SWZ128(base + g * 8)) = make_uint2(h01, h23);
        }
    };

    stageB(0, smb);
    CPCOMMIT();
    stageP(0, sm);

    for (int c = 0; c < 32; ++c) {
        const int p = c & 1;
        const uint32_t bufa = smb + p * BUFSZ;
        char* bufn = sm + (p ^ 1) * BUFSZ;

        if (c < 31) {
            stageB(c + 1, smb + (p ^ 1) * BUFSZ);
            CPCOMMIT();
            stageP(c + 1, bufn);
            CPWAIT1();
        } else {
            CPWAIT0();
        }
        __syncthreads();

#pragma unroll
        for (int k16 = 0; k16 < 4; ++k16) {
            uint32_t ah[2][4];
#pragma unroll
            for (int mt = 0; mt < 2; ++mt)
                ldsm4(ah[mt], bufa + O_PH +
                      SWZ128(a_l + (uint32_t)(mt * 2048 + k16 * 32)));
#pragma unroll
            for (int nt2 = 0; nt2 < 4; ++nt2) {
                uint32_t bo = SWZ128(b_l + (uint32_t)(nt2 * 2048 + k16 * 32));
                uint32_t bh[4];
                ldsm4(bh, bufa + O_BH + bo);
#pragma unroll
                for (int mt = 0; mt < 2; ++mt) {
                    mmaf16(acc[mt][nt2 * 2 + 0], ah[mt], bh);
                    mmaf16(acc[mt][nt2 * 2 + 1], ah[mt], bh + 2);
                }
            }
        }
        __syncthreads();
    }

    // ---- Z reduce: 4 threads (jq) share prow; lanes 4-aligned ----
    float* zs = (float*)sm;
    zacc += __shfl_xor_sync(0xffffffffu, zacc, 1);
    zacc += __shfl_xor_sync(0xffffffffu, zacc, 2);
    if (jq == 0) zs[prow] = 1.0f / zacc;    // diag in mask -> zacc > 0
    __syncthreads();

    // ---- epilogue: normalize + ELU + store ----
    const int tq = lane >> 2, tr = lane & 3;
#pragma unroll
    for (int mt = 0; mt < 2; ++mt) {
        int il = wm * 32 + mt * 16 + tq;
        float iz0 = zs[il], iz1 = zs[il + 8];
        int i = i0 + il;
        float* op0 = out + ((size_t)bz * NN + i) * FF + wn * 64 + tr * 2;
#pragma unroll
        for (int nt = 0; nt < 8; ++nt) {
            float2 v0 = make_float2(elu1(acc[mt][nt][0] * iz0),
                                    elu1(acc[mt][nt][1] * iz0));
            float2 v1 = make_float2(elu1(acc[mt][nt][2] * iz1),
                                    elu1(acc[mt][nt][3] * iz1));
            *(float2*)(op0 + nt * 8) = v0;
            *(float2*)(op0 + nt * 8 + 8 * FF) = v1;
        }
    }
}

// ========================================================================
extern "C" void kernel_launch(void* const* d_in, const int* in_sizes, int n_in,
                              void* d_out, int out_size) {
    const float* h   = (const float*)d_in[0];
    const int*   adj = (const int*)d_in[1];
    const float* W   = (const float*)d_in[2];
    const float* a   = (const float*)d_in[3];
    float* out = (float*)d_out;

    cudaFuncSetAttribute(k_gemm1, cudaFuncAttributeMaxDynamicSharedMemorySize, 66560);
    cudaFuncSetAttribute(k_attn, cudaFuncAttributeMaxDynamicSharedMemorySize, 2 * BUFSZ);

    k_packW<<<FF, FF>>>(W);
    k_mask <<<NN * 128 / 256, 256>>>(adj);
    k_gemm1<<<dim3(128, 2), 256, 66560>>>(h, a);
    k_smax <<<BB, 256>>>();
    k_attn <<<dim3(NN / 64, BB), 256, 2 * BUFSZ>>>(out);
}